// round 5
// baseline (speedup 1.0000x reference)
#include <cuda_runtime.h>
#include <cuda_bf16.h>

// Problem constants
#define Bsz 2
#define E 2048
#define C 512
#define H 8
#define D 64
#define M_TOT (Bsz * E)       // 4096
#define CAP 320               // per-row nnz capacity (mean ~102)
#define QKVC 1536             // fused q|k|v row length

// ---------------- scratch (device globals; no allocation) ----------------
__device__ float  g_qkv[M_TOT * QKVC];  // [b*E+e][ q(0:512) | k(512:1024) | v(1024:1536) ]
__device__ float  g_o[M_TOT * C];
__device__ float  g_p[M_TOT * C];
__device__ int    g_cnt[E];
__device__ float2 g_pair[E * CAP];      // (idx-as-bits, maskval)
__device__ float  g_vsum[Bsz * C];

// =============== tf32 tensor-core GEMM v3 =================================
// C[m, coloff+n] = sum_k A[m,k]*B[n,k]. 128x64x16 tiles, double-buffered,
// 128 threads = 4 warps (2m x 2n), warp tile 64x32, mma m16n8k8 tf32.
#define GM 128
#define GN 64
#define GK 16
#define SA 136   // padded m stride
#define SB 72    // padded n stride

__device__ __forceinline__ unsigned f2tf(float f) {
    unsigned r;
    asm("cvt.rna.tf32.f32 %0, %1;" : "=r"(r) : "f"(f));
    return r;
}

__device__ __forceinline__ void mma_tf32(float* c, const unsigned* a, const unsigned* b) {
    asm volatile(
        "mma.sync.aligned.m16n8k8.row.col.f32.tf32.tf32.f32 "
        "{%0,%1,%2,%3}, {%4,%5,%6,%7}, {%8,%9}, {%0,%1,%2,%3};\n"
        : "+f"(c[0]), "+f"(c[1]), "+f"(c[2]), "+f"(c[3])
        : "r"(a[0]), "r"(a[1]), "r"(a[2]), "r"(a[3]), "r"(b[0]), "r"(b[1]));
}

__global__ __launch_bounds__(128) void gemm_tf32_v3(
    const float* __restrict__ A,
    const float* __restrict__ B0, const float* __restrict__ B1, const float* __restrict__ B2,
    float* __restrict__ Cc, int ldc, int coloff_mul, int K)
{
    int z = blockIdx.z;
    const float* Bm = (z == 0) ? B0 : (z == 1 ? B1 : B2);
    int coloff = z * coloff_mul;

    __shared__ float As[2][GK][SA];
    __shared__ float Bs[2][GK][SB];

    int tid  = threadIdx.x;
    int lane = tid & 31;
    int warp = tid >> 5;
    int m0 = blockIdx.y * GM;
    int n0 = blockIdx.x * GN;

    // A loader: one thread per row, 16 consecutive k
    const float* Ag = A + (size_t)(m0 + tid) * K;
    // B loader: 2 threads per row, 8 consecutive k each
    int br = tid >> 1, bc = (tid & 1) * 8;
    const float* Bg = Bm + (size_t)(n0 + br) * K + bc;

    int m_base = (warp >> 1) * 64;
    int n_base = (warp & 1) * 32;
    int lrow = lane >> 2;          // 0..7
    int lcol = lane & 3;           // 0..3

    float acc[4][4][4];
    #pragma unroll
    for (int mi = 0; mi < 4; mi++)
        #pragma unroll
        for (int ni = 0; ni < 4; ni++)
            #pragma unroll
            for (int r = 0; r < 4; r++) acc[mi][ni][r] = 0.0f;

    const int nt = K / GK;   // 32

    float4 pa[4], pb[2];
    #pragma unroll
    for (int j = 0; j < 4; j++) pa[j] = *reinterpret_cast<const float4*>(Ag + 4 * j);
    #pragma unroll
    for (int j = 0; j < 2; j++) pb[j] = *reinterpret_cast<const float4*>(Bg + 4 * j);

    #pragma unroll
    for (int j = 0; j < 4; j++) {
        As[0][4 * j + 0][tid] = __uint_as_float(f2tf(pa[j].x));
        As[0][4 * j + 1][tid] = __uint_as_float(f2tf(pa[j].y));
        As[0][4 * j + 2][tid] = __uint_as_float(f2tf(pa[j].z));
        As[0][4 * j + 3][tid] = __uint_as_float(f2tf(pa[j].w));
    }
    #pragma unroll
    for (int j = 0; j < 2; j++) {
        Bs[0][bc + 4 * j + 0][br] = __uint_as_float(f2tf(pb[j].x));
        Bs[0][bc + 4 * j + 1][br] = __uint_as_float(f2tf(pb[j].y));
        Bs[0][bc + 4 * j + 2][br] = __uint_as_float(f2tf(pb[j].z));
        Bs[0][bc + 4 * j + 3][br] = __uint_as_float(f2tf(pb[j].w));
    }
    __syncthreads();

    for (int kt = 0; kt < nt; kt++) {
        int cur = kt & 1;
        bool more = (kt + 1) < nt;
        if (more) {
            const float* Ap = Ag + (kt + 1) * GK;
            const float* Bp = Bg + (kt + 1) * GK;
            #pragma unroll
            for (int j = 0; j < 4; j++) pa[j] = *reinterpret_cast<const float4*>(Ap + 4 * j);
            #pragma unroll
            for (int j = 0; j < 2; j++) pb[j] = *reinterpret_cast<const float4*>(Bp + 4 * j);
        }

        #pragma unroll
        for (int ks = 0; ks < 2; ks++) {
            int k0 = ks * 8;
            unsigned afr[4][4];
            #pragma unroll
            for (int mi = 0; mi < 4; mi++) {
                int row = m_base + mi * 16 + lrow;
                afr[mi][0] = __float_as_uint(As[cur][k0 + lcol][row]);
                afr[mi][1] = __float_as_uint(As[cur][k0 + lcol][row + 8]);
                afr[mi][2] = __float_as_uint(As[cur][k0 + lcol + 4][row]);
                afr[mi][3] = __float_as_uint(As[cur][k0 + lcol + 4][row + 8]);
            }
            unsigned bfr[4][2];
            #pragma unroll
            for (int ni = 0; ni < 4; ni++) {
                int nn2 = n_base + ni * 8 + lrow;
                bfr[ni][0] = __float_as_uint(Bs[cur][k0 + lcol][nn2]);
                bfr[ni][1] = __float_as_uint(Bs[cur][k0 + lcol + 4][nn2]);
            }
            #pragma unroll
            for (int mi = 0; mi < 4; mi++)
                #pragma unroll
                for (int ni = 0; ni < 4; ni++)
                    mma_tf32(acc[mi][ni], afr[mi], bfr[ni]);
        }

        if (more) {
            int nxt = cur ^ 1;
            #pragma unroll
            for (int j = 0; j < 4; j++) {
                As[nxt][4 * j + 0][tid] = __uint_as_float(f2tf(pa[j].x));
                As[nxt][4 * j + 1][tid] = __uint_as_float(f2tf(pa[j].y));
                As[nxt][4 * j + 2][tid] = __uint_as_float(f2tf(pa[j].z));
                As[nxt][4 * j + 3][tid] = __uint_as_float(f2tf(pa[j].w));
            }
            #pragma unroll
            for (int j = 0; j < 2; j++) {
                Bs[nxt][bc + 4 * j + 0][br] = __uint_as_float(f2tf(pb[j].x));
                Bs[nxt][bc + 4 * j + 1][br] = __uint_as_float(f2tf(pb[j].y));
                Bs[nxt][bc + 4 * j + 2][br] = __uint_as_float(f2tf(pb[j].z));
                Bs[nxt][bc + 4 * j + 3][br] = __uint_as_float(f2tf(pb[j].w));
            }
            __syncthreads();
        }
    }

    #pragma unroll
    for (int mi = 0; mi < 4; mi++) {
        #pragma unroll
        for (int ni = 0; ni < 4; ni++) {
            int r  = m0 + m_base + mi * 16 + lrow;
            int cc = coloff + n0 + n_base + ni * 8 + lcol * 2;
            *reinterpret_cast<float2*>(Cc + (size_t)r * ldc + cc) =
                make_float2(acc[mi][ni][0], acc[mi][ni][1]);
            *reinterpret_cast<float2*>(Cc + (size_t)(r + 8) * ldc + cc) =
                make_float2(acc[mi][ni][2], acc[mi][ni][3]);
        }
    }
}

// ---------------- mask -> per-row compressed (idx,val) pairs ---------------
__global__ __launch_bounds__(128) void build_csr(const float* __restrict__ mask)
{
    int row  = blockIdx.x * 4 + (threadIdx.x >> 5);
    int lane = threadIdx.x & 31;
    if (row >= E) return;

    int cnt = 0;
    const float* mrow = mask + (size_t)row * E;
    for (int j0 = 0; j0 < E; j0 += 32) {
        float v = mrow[j0 + lane];
        unsigned bal = __ballot_sync(0xFFFFFFFFu, v != 0.0f);
        if (v != 0.0f) {
            int off = cnt + __popc(bal & ((1u << lane) - 1u));
            if (off < CAP) {
                g_pair[row * CAP + off] = make_float2(__int_as_float(j0 + lane), v);
            }
        }
        cnt += __popc(bal);
    }
    if (lane == 0) g_cnt[row] = (cnt > CAP) ? CAP : cnt;
}

// ---------------- vsum[b][h*64+d] = sum_e v[b,e,h,d] ----------------------
__global__ __launch_bounds__(512) void vsum_kernel()
{
    int bh = blockIdx.x;           // 0..15
    int b = bh >> 3, h = bh & 7;
    int d  = threadIdx.x & 63;
    int sl = threadIdx.x >> 6;     // 0..7
    const float* vb = g_qkv + (size_t)b * E * QKVC + 1024 + h * D + d;
    float s = 0.0f;
    #pragma unroll 4
    for (int e = sl; e < E; e += 8) s += vb[(size_t)e * QKVC];
    __shared__ float red[8][64];
    red[sl][d] = s;
    __syncthreads();
    if (sl == 0) {
        float t = 0.0f;
        #pragma unroll
        for (int i = 0; i < 8; i++) t += red[i][d];
        g_vsum[b * C + h * D + d] = t;
    }
}

// ---------------- sparse masked attention v4b: smem-chunked -----------------
// Block = (b,h) x 64-query tile. Loop over 32 chunks of 64 keys:
// stage K/V chunk (this head) in smem (32KB total), then 16-lane groups
// gather via LDS.128. CSR lists are sorted, so a cursor walk partitions them.
#define TQ 64
#define KC 64
#define NCH (E / KC)   // 32

__global__ __launch_bounds__(256) void attn_sparse4()
{
    __shared__ float sk[KC * D];   // 16 KB
    __shared__ float sv[KC * D];   // 16 KB

    int bh = blockIdx.x;
    int b = bh >> 3, h = bh & 7;
    int q0 = blockIdx.y * TQ;
    int tid  = threadIdx.x;
    int gid  = tid >> 4;            // group 0..15
    int gl   = tid & 15;            // lane in group
    unsigned gmask = 0xFFFFu << ((gid & 1) * 16);
    int gsh = (gid & 1) * 16;

    size_t batch_base = (size_t)b * E * QKVC;

    // per-group queries: q0 + gid*4 + j
    float4 qv[4];
    float4 acc[4];
    int cur[4], n[4];
    {
        float4 vs = *reinterpret_cast<const float4*>(g_vsum + b * C + h * D + gl * 4);
        #pragma unroll
        for (int j = 0; j < 4; j++) {
            int q = q0 + gid * 4 + j;
            qv[j] = *reinterpret_cast<const float4*>(
                g_qkv + batch_base + (size_t)q * QKVC + h * D + gl * 4);
            acc[j] = make_float4(0.5f * vs.x, 0.5f * vs.y, 0.5f * vs.z, 0.5f * vs.w);
            cur[j] = 0;
            n[j]   = g_cnt[q];
        }
    }

    for (int ch = 0; ch < NCH; ch++) {
        int kbase = ch * KC;
        int kend  = kbase + KC;

        __syncthreads();
        // stage chunk: 256 threads cover 2 arrays x 64 rows x 2 half-rows
        {
            int sel  = tid >> 7;                 // 0 = k, 1 = v
            int t2   = tid & 127;
            int r    = t2 >> 1;                  // 0..63
            int half = (t2 & 1) * 32;            // 0 or 32 floats
            const float* src = g_qkv + batch_base + (size_t)(kbase + r) * QKVC
                               + 512 + sel * 512 + h * D + half;
            float* dst = (sel ? sv : sk) + r * D + half;
            #pragma unroll
            for (int i = 0; i < 8; i++)
                *reinterpret_cast<float4*>(dst + i * 4) =
                    *reinterpret_cast<const float4*>(src + i * 4);
        }
        __syncthreads();

        #pragma unroll 1
        for (int j = 0; j < 4; j++) {
            const float2* plist = g_pair + (q0 + gid * 4 + j) * CAP;
            while (true) {
                int idx = cur[j] + gl;
                float2 pr;
                int ki;
                if (idx < n[j]) {
                    pr = plist[idx];
                    ki = __float_as_int(pr.x);
                } else {
                    pr.y = 0.0f;
                    ki = 0x7FFFFFFF;
                }
                bool valid = ki < kend;
                unsigned bal = __ballot_sync(gmask, valid);
                int cnt = __popc((bal >> gsh) & 0xFFFFu);

                for (int t = 0; t < cnt; t++) {
                    int   kit = __shfl_sync(gmask, ki, t, 16);
                    float mv  = __shfl_sync(gmask, pr.y, t, 16);
                    int rr = kit - kbase;
                    float4 kk = *reinterpret_cast<const float4*>(sk + rr * D + gl * 4);
                    float p = qv[j].x * kk.x + qv[j].y * kk.y
                            + qv[j].z * kk.z + qv[j].w * kk.w;
                    p += __shfl_xor_sync(gmask, p, 1, 16);
                    p += __shfl_xor_sync(gmask, p, 2, 16);
                    p += __shfl_xor_sync(gmask, p, 4, 16);
                    p += __shfl_xor_sync(gmask, p, 8, 16);
                    float s = 0.5f * mv * p;
                    float4 vvv = *reinterpret_cast<const float4*>(sv + rr * D + gl * 4);
                    acc[j].x += s * vvv.x;
                    acc[j].y += s * vvv.y;
                    acc[j].z += s * vvv.z;
                    acc[j].w += s * vvv.w;
                }
                cur[j] += cnt;
                if (cnt < 16) break;   // rest of this sorted list is >= kend
            }
        }
    }

    #pragma unroll
    for (int j = 0; j < 4; j++) {
        int q = q0 + gid * 4 + j;
        *reinterpret_cast<float4*>(
            g_o + ((size_t)(b * E + q)) * C + h * D + gl * 4) = acc[j];
    }
}

// ---------------- bias + LayerNorm + residual ------------------------------
__global__ __launch_bounds__(128) void ln_residual(
    const float* __restrict__ x,  const float* __restrict__ bp,
    const float* __restrict__ w,  const float* __restrict__ bb,
    const float* __restrict__ gamma, float* __restrict__ out)
{
    int row = blockIdx.x;          // 0..4095
    int tid = threadIdx.x;         // 128
    const float* pr = g_p + (size_t)row * C;

    float y[4];
    float sum = 0.0f, sq = 0.0f;
    #pragma unroll
    for (int i = 0; i < 4; i++) {
        int c = tid + i * 128;
        y[i] = pr[c] + bp[c];
        sum += y[i];
        sq  += y[i] * y[i];
    }
    #pragma unroll
    for (int o = 16; o; o >>= 1) {
        sum += __shfl_xor_sync(0xFFFFFFFFu, sum, o);
        sq  += __shfl_xor_sync(0xFFFFFFFFu, sq,  o);
    }
    __shared__ float s1[4], s2[4];
    int wid = tid >> 5, lane = tid & 31;
    if (lane == 0) { s1[wid] = sum; s2[wid] = sq; }
    __syncthreads();
    float tot  = s1[0] + s1[1] + s1[2] + s1[3];
    float totq = s2[0] + s2[1] + s2[2] + s2[3];

    float mu  = tot * (1.0f / C);
    float var = totq * (1.0f / C) - mu * mu;
    float rs  = rsqrtf(var + 1e-5f);
    float gm  = gamma[0];

    #pragma unroll
    for (int i = 0; i < 4; i++) {
        int c = tid + i * 128;
        float ln = (y[i] - mu) * rs * w[c] + bb[c];
        out[(size_t)row * C + c] = x[(size_t)row * C + c] + gm * ln;
    }
}

// ---------------- launch ----------------------------------------------------
extern "C" void kernel_launch(void* const* d_in, const int* in_sizes, int n_in,
                              void* d_out, int out_size)
{
    const float* x     = (const float*)d_in[0];
    const float* mask  = (const float*)d_in[1];
    const float* Wq    = (const float*)d_in[2];
    const float* Wk    = (const float*)d_in[3];
    const float* Wv    = (const float*)d_in[4];
    const float* Wp    = (const float*)d_in[5];
    const float* bp    = (const float*)d_in[6];
    const float* lnw   = (const float*)d_in[7];
    const float* lnb   = (const float*)d_in[8];
    const float* gamma = (const float*)d_in[9];
    float* out = (float*)d_out;

    float *qkvp, *op, *pp;
    cudaGetSymbolAddress((void**)&qkvp, g_qkv);
    cudaGetSymbolAddress((void**)&op, g_o);
    cudaGetSymbolAddress((void**)&pp, g_p);

    // 1) fused QKV projection into g_qkv[M][1536]
    gemm_tf32_v3<<<dim3(C / GN, M_TOT / GM, 3), 128>>>(
        x, Wq, Wk, Wv, qkvp, QKVC, 512, C);

    // 2) mask compression
    build_csr<<<E / 4, 128>>>(mask);

    // 3) per-(b,h) V column sums
    vsum_kernel<<<Bsz * H, 512>>>();

    // 4) sparse masked attention: smem-chunked
    attn_sparse4<<<dim3(Bsz * H, E / TQ), 256>>>();

    // 5) output projection
    gemm_tf32_v3<<<dim3(C / GN, M_TOT / GM, 1), 128>>>(
        op, Wp, Wp, Wp, pp, C, 0, C);

    // 6) bias + LN + residual
    ln_residual<<<M_TOT, 128>>>(x, bp, lnw, lnb, gamma, out);
}

// round 6
// speedup vs baseline: 3.3252x; 3.3252x over previous
#include <cuda_runtime.h>
#include <cuda_bf16.h>

// Problem constants
#define Bsz 2
#define E 2048
#define C 512
#define H 8
#define D 64
#define M_TOT (Bsz * E)       // 4096
#define CAP 320               // per-row nnz capacity (mean ~102)
#define QKVC 1536             // fused q|k|v row length
#define KV16C 1024            // bf16 k|v row length

// ---------------- scratch (device globals; no allocation) ----------------
__device__ float          g_qkv[M_TOT * QKVC]; // [row][ q | k | v ] fp32
__device__ __nv_bfloat16  g_kv16[M_TOT * KV16C]; // [row][ k(0:512) | v(512:1024) ] bf16
__device__ float          g_o[M_TOT * C];
__device__ float          g_p[M_TOT * C];
__device__ int            g_cnt[E];
__device__ float2         g_pair[E * CAP];     // (idx-as-bits, maskval), sorted by idx
__device__ float          g_vsum[Bsz * C];

// =============== tf32 tensor-core GEMM (v2, 256 threads) ==================
// C[m, coloff+n] = sum_k A[m,k]*B[n,k].  128x128x16 tiles, double-buffered,
// 256 threads = 8 warps (2m x 4n), warp tile 64x32, mma m16n8k8 tf32.
// When writing k (z=1) / v (z=2) of the fused QKV, also emits bf16 copies.
#define GM 128
#define GN 128
#define GK 16
#define GSAP 136

__device__ __forceinline__ unsigned f2tf(float f) {
    unsigned r;
    asm("cvt.rna.tf32.f32 %0, %1;" : "=r"(r) : "f"(f));
    return r;
}

__device__ __forceinline__ void mma_tf32(float* c, const unsigned* a, const unsigned* b) {
    asm volatile(
        "mma.sync.aligned.m16n8k8.row.col.f32.tf32.tf32.f32 "
        "{%0,%1,%2,%3}, {%4,%5,%6,%7}, {%8,%9}, {%0,%1,%2,%3};\n"
        : "+f"(c[0]), "+f"(c[1]), "+f"(c[2]), "+f"(c[3])
        : "r"(a[0]), "r"(a[1]), "r"(a[2]), "r"(a[3]), "r"(b[0]), "r"(b[1]));
}

__global__ __launch_bounds__(256) void gemm_tf32_v2(
    const float* __restrict__ A,
    const float* __restrict__ B0, const float* __restrict__ B1, const float* __restrict__ B2,
    float* __restrict__ Cc, int ldc, int coloff_mul, int K)
{
    int z = blockIdx.z;
    const float* Bm = (z == 0) ? B0 : (z == 1 ? B1 : B2);
    int coloff = z * coloff_mul;
    bool wkv = (coloff_mul != 0) && (z >= 1);   // also write bf16 k/v copy
    int kvoff = (z - 1) * 512;                  // 0 for k, 512 for v

    __shared__ float As[2][GK][GSAP];
    __shared__ float Bs[2][GK][GSAP];

    int tid  = threadIdx.x;
    int lane = tid & 31;
    int warp = tid >> 5;
    int m0 = blockIdx.y * GM;
    int n0 = blockIdx.x * GN;

    int lr = tid >> 1;             // 0..127
    int lc = (tid & 1) * 8;        // 0 or 8
    const float* Ag = A  + (size_t)(m0 + lr) * K + lc;
    const float* Bg = Bm + (size_t)(n0 + lr) * K + lc;

    int m_base = (warp >> 2) * 64;
    int n_base = (warp & 3) * 32;
    int lrow = lane >> 2;          // 0..7
    int lcol = lane & 3;           // 0..3

    float acc[4][4][4];
    #pragma unroll
    for (int mi = 0; mi < 4; mi++)
        #pragma unroll
        for (int ni = 0; ni < 4; ni++)
            #pragma unroll
            for (int r = 0; r < 4; r++) acc[mi][ni][r] = 0.0f;

    const int nt = K / GK;   // 32

    float4 pa[2], pb[2];
    pa[0] = *reinterpret_cast<const float4*>(Ag);
    pa[1] = *reinterpret_cast<const float4*>(Ag + 4);
    pb[0] = *reinterpret_cast<const float4*>(Bg);
    pb[1] = *reinterpret_cast<const float4*>(Bg + 4);

    #pragma unroll
    for (int j = 0; j < 2; j++) {
        As[0][lc + 4 * j + 0][lr] = __uint_as_float(f2tf(pa[j].x));
        As[0][lc + 4 * j + 1][lr] = __uint_as_float(f2tf(pa[j].y));
        As[0][lc + 4 * j + 2][lr] = __uint_as_float(f2tf(pa[j].z));
        As[0][lc + 4 * j + 3][lr] = __uint_as_float(f2tf(pa[j].w));
        Bs[0][lc + 4 * j + 0][lr] = __uint_as_float(f2tf(pb[j].x));
        Bs[0][lc + 4 * j + 1][lr] = __uint_as_float(f2tf(pb[j].y));
        Bs[0][lc + 4 * j + 2][lr] = __uint_as_float(f2tf(pb[j].z));
        Bs[0][lc + 4 * j + 3][lr] = __uint_as_float(f2tf(pb[j].w));
    }
    __syncthreads();

    for (int kt = 0; kt < nt; kt++) {
        int cur = kt & 1;
        bool more = (kt + 1) < nt;
        if (more) {
            const float* Ap = Ag + (kt + 1) * GK;
            const float* Bp = Bg + (kt + 1) * GK;
            pa[0] = *reinterpret_cast<const float4*>(Ap);
            pa[1] = *reinterpret_cast<const float4*>(Ap + 4);
            pb[0] = *reinterpret_cast<const float4*>(Bp);
            pb[1] = *reinterpret_cast<const float4*>(Bp + 4);
        }

        #pragma unroll
        for (int ks = 0; ks < 2; ks++) {
            int k0 = ks * 8;
            unsigned afr[4][4];
            #pragma unroll
            for (int mi = 0; mi < 4; mi++) {
                int row = m_base + mi * 16 + lrow;
                afr[mi][0] = __float_as_uint(As[cur][k0 + lcol][row]);
                afr[mi][1] = __float_as_uint(As[cur][k0 + lcol][row + 8]);
                afr[mi][2] = __float_as_uint(As[cur][k0 + lcol + 4][row]);
                afr[mi][3] = __float_as_uint(As[cur][k0 + lcol + 4][row + 8]);
            }
            unsigned bfr[4][2];
            #pragma unroll
            for (int ni = 0; ni < 4; ni++) {
                int nn2 = n_base + ni * 8 + lrow;
                bfr[ni][0] = __float_as_uint(Bs[cur][k0 + lcol][nn2]);
                bfr[ni][1] = __float_as_uint(Bs[cur][k0 + lcol + 4][nn2]);
            }
            #pragma unroll
            for (int mi = 0; mi < 4; mi++)
                #pragma unroll
                for (int ni = 0; ni < 4; ni++)
                    mma_tf32(acc[mi][ni], afr[mi], bfr[ni]);
        }

        if (more) {
            int nxt = cur ^ 1;
            #pragma unroll
            for (int j = 0; j < 2; j++) {
                As[nxt][lc + 4 * j + 0][lr] = __uint_as_float(f2tf(pa[j].x));
                As[nxt][lc + 4 * j + 1][lr] = __uint_as_float(f2tf(pa[j].y));
                As[nxt][lc + 4 * j + 2][lr] = __uint_as_float(f2tf(pa[j].z));
                As[nxt][lc + 4 * j + 3][lr] = __uint_as_float(f2tf(pa[j].w));
                Bs[nxt][lc + 4 * j + 0][lr] = __uint_as_float(f2tf(pb[j].x));
                Bs[nxt][lc + 4 * j + 1][lr] = __uint_as_float(f2tf(pb[j].y));
                Bs[nxt][lc + 4 * j + 2][lr] = __uint_as_float(f2tf(pb[j].z));
                Bs[nxt][lc + 4 * j + 3][lr] = __uint_as_float(f2tf(pb[j].w));
            }
            __syncthreads();
        }
    }

    // epilogue: fp32 always; bf16 side-copy for k/v
    #pragma unroll
    for (int mi = 0; mi < 4; mi++) {
        #pragma unroll
        for (int ni = 0; ni < 4; ni++) {
            int r   = m0 + m_base + mi * 16 + lrow;
            int cn  = n0 + n_base + ni * 8 + lcol * 2;
            int cc  = coloff + cn;
            float2 s0 = make_float2(acc[mi][ni][0], acc[mi][ni][1]);
            float2 s1 = make_float2(acc[mi][ni][2], acc[mi][ni][3]);
            *reinterpret_cast<float2*>(Cc + (size_t)r * ldc + cc)       = s0;
            *reinterpret_cast<float2*>(Cc + (size_t)(r + 8) * ldc + cc) = s1;
            if (wkv) {
                int cb = kvoff + cn;
                *reinterpret_cast<__nv_bfloat162*>(g_kv16 + (size_t)r * KV16C + cb) =
                    __float22bfloat162_rn(s0);
                *reinterpret_cast<__nv_bfloat162*>(g_kv16 + (size_t)(r + 8) * KV16C + cb) =
                    __float22bfloat162_rn(s1);
            }
        }
    }
}

// ---------------- mask -> per-row compressed (idx,val) pairs ---------------
__global__ __launch_bounds__(128) void build_csr(const float* __restrict__ mask)
{
    int row  = blockIdx.x * 4 + (threadIdx.x >> 5);
    int lane = threadIdx.x & 31;
    if (row >= E) return;

    int cnt = 0;
    const float* mrow = mask + (size_t)row * E;
    for (int j0 = 0; j0 < E; j0 += 32) {
        float v = mrow[j0 + lane];
        unsigned bal = __ballot_sync(0xFFFFFFFFu, v != 0.0f);
        if (v != 0.0f) {
            int off = cnt + __popc(bal & ((1u << lane) - 1u));
            if (off < CAP) {
                g_pair[row * CAP + off] = make_float2(__int_as_float(j0 + lane), v);
            }
        }
        cnt += __popc(bal);
    }
    if (lane == 0) g_cnt[row] = (cnt > CAP) ? CAP : cnt;
}

// ---------------- vsum[b][h*64+d] = sum_e v[b,e,h,d]  (fp32, exact) -------
__global__ __launch_bounds__(512) void vsum_kernel()
{
    int bh = blockIdx.x;           // 0..15
    int b = bh >> 3, h = bh & 7;
    int d  = threadIdx.x & 63;
    int sl = threadIdx.x >> 6;     // 0..7
    const float* vb = g_qkv + (size_t)b * E * QKVC + 1024 + h * D + d;
    float s = 0.0f;
    #pragma unroll 4
    for (int e = sl; e < E; e += 8) s += vb[(size_t)e * QKVC];
    __shared__ float red[8][64];
    red[sl][d] = s;
    __syncthreads();
    if (sl == 0) {
        float t = 0.0f;
        #pragma unroll
        for (int i = 0; i < 8; i++) t += red[i][d];
        g_vsum[b * C + h * D + d] = t;
    }
}

// ---------------- sparse masked attention v5: bf16 gather ------------------
// Block (128 thr) per query q: 2 batches x 64 threads; thread owns 8 channels
// (one LDG.128 of bf16x8 per k-row and per v-row per nnz). Dot reduces over
// 8 lanes (one head = 64 ch = 8 threads). Unroll 4 nnz for MLP.
__device__ __forceinline__ void bf8_to_f(uint4 r, float* f) {
    float2 a = __bfloat1622float2(*reinterpret_cast<__nv_bfloat162*>(&r.x));
    float2 b = __bfloat1622float2(*reinterpret_cast<__nv_bfloat162*>(&r.y));
    float2 c = __bfloat1622float2(*reinterpret_cast<__nv_bfloat162*>(&r.z));
    float2 d = __bfloat1622float2(*reinterpret_cast<__nv_bfloat162*>(&r.w));
    f[0] = a.x; f[1] = a.y; f[2] = b.x; f[3] = b.y;
    f[4] = c.x; f[5] = c.y; f[6] = d.x; f[7] = d.y;
}

__global__ __launch_bounds__(128) void attn_sparse5()
{
    __shared__ float2 sp[CAP];

    int q   = blockIdx.x;
    int tid = threadIdx.x;        // 0..127
    int bb  = tid >> 6;           // batch 0/1
    int t   = tid & 63;
    int c0  = t * 8;              // channel start (head = c0/64)

    int n    = g_cnt[q];
    int npad = (n + 3) & ~3;
    for (int i = tid; i < npad; i += 128)
        sp[i] = (i < n) ? g_pair[q * CAP + i] : make_float2(__int_as_float(0), 0.0f);
    __syncthreads();

    size_t qrow = ((size_t)(bb * E + q)) * QKVC;
    float qv[8];
    *reinterpret_cast<float4*>(qv)     = *reinterpret_cast<const float4*>(g_qkv + qrow + c0);
    *reinterpret_cast<float4*>(qv + 4) = *reinterpret_cast<const float4*>(g_qkv + qrow + c0 + 4);

    float acc[8];
    {
        float4 a = *reinterpret_cast<const float4*>(g_vsum + bb * C + c0);
        float4 b = *reinterpret_cast<const float4*>(g_vsum + bb * C + c0 + 4);
        acc[0] = 0.5f * a.x; acc[1] = 0.5f * a.y; acc[2] = 0.5f * a.z; acc[3] = 0.5f * a.w;
        acc[4] = 0.5f * b.x; acc[5] = 0.5f * b.y; acc[6] = 0.5f * b.z; acc[7] = 0.5f * b.w;
    }

    const __nv_bfloat16* kvb = g_kv16 + (size_t)bb * E * KV16C;

    for (int i = 0; i < npad; i += 4) {
        float2 pr0 = sp[i], pr1 = sp[i + 1], pr2 = sp[i + 2], pr3 = sp[i + 3];
        int i0 = __float_as_int(pr0.x);
        int i1 = __float_as_int(pr1.x);
        int i2 = __float_as_int(pr2.x);
        int i3 = __float_as_int(pr3.x);

        const __nv_bfloat16* r0 = kvb + (size_t)i0 * KV16C + c0;
        const __nv_bfloat16* r1 = kvb + (size_t)i1 * KV16C + c0;
        const __nv_bfloat16* r2 = kvb + (size_t)i2 * KV16C + c0;
        const __nv_bfloat16* r3 = kvb + (size_t)i3 * KV16C + c0;

        uint4 kr0 = *reinterpret_cast<const uint4*>(r0);
        uint4 kr1 = *reinterpret_cast<const uint4*>(r1);
        uint4 kr2 = *reinterpret_cast<const uint4*>(r2);
        uint4 kr3 = *reinterpret_cast<const uint4*>(r3);
        uint4 vr0 = *reinterpret_cast<const uint4*>(r0 + 512);
        uint4 vr1 = *reinterpret_cast<const uint4*>(r1 + 512);
        uint4 vr2 = *reinterpret_cast<const uint4*>(r2 + 512);
        uint4 vr3 = *reinterpret_cast<const uint4*>(r3 + 512);

        float k0[8], k1[8], k2[8], k3[8];
        bf8_to_f(kr0, k0); bf8_to_f(kr1, k1); bf8_to_f(kr2, k2); bf8_to_f(kr3, k3);

        float p0 = 0.f, p1 = 0.f, p2 = 0.f, p3 = 0.f;
        #pragma unroll
        for (int j = 0; j < 8; j++) {
            p0 += qv[j] * k0[j];
            p1 += qv[j] * k1[j];
            p2 += qv[j] * k2[j];
            p3 += qv[j] * k3[j];
        }
        // reduce across the 8 lanes of this head
        #pragma unroll
        for (int o = 1; o < 8; o <<= 1) {
            p0 += __shfl_xor_sync(0xFFFFFFFFu, p0, o, 8);
            p1 += __shfl_xor_sync(0xFFFFFFFFu, p1, o, 8);
            p2 += __shfl_xor_sync(0xFFFFFFFFu, p2, o, 8);
            p3 += __shfl_xor_sync(0xFFFFFFFFu, p3, o, 8);
        }

        float s0 = 0.5f * pr0.y * p0;
        float s1 = 0.5f * pr1.y * p1;
        float s2 = 0.5f * pr2.y * p2;
        float s3 = 0.5f * pr3.y * p3;

        float v0[8], v1[8], v2[8], v3[8];
        bf8_to_f(vr0, v0); bf8_to_f(vr1, v1); bf8_to_f(vr2, v2); bf8_to_f(vr3, v3);

        #pragma unroll
        for (int j = 0; j < 8; j++)
            acc[j] += s0 * v0[j] + s1 * v1[j] + s2 * v2[j] + s3 * v3[j];
    }

    float* orow = g_o + ((size_t)(bb * E + q)) * C + c0;
    *reinterpret_cast<float4*>(orow)     = *reinterpret_cast<float4*>(acc);
    *reinterpret_cast<float4*>(orow + 4) = *reinterpret_cast<float4*>(acc + 4);
}

// ---------------- bias + LayerNorm + residual ------------------------------
__global__ __launch_bounds__(128) void ln_residual(
    const float* __restrict__ x,  const float* __restrict__ bp,
    const float* __restrict__ w,  const float* __restrict__ bb,
    const float* __restrict__ gamma, float* __restrict__ out)
{
    int row = blockIdx.x;          // 0..4095
    int tid = threadIdx.x;         // 128
    const float* pr = g_p + (size_t)row * C;

    float y[4];
    float sum = 0.0f, sq = 0.0f;
    #pragma unroll
    for (int i = 0; i < 4; i++) {
        int c = tid + i * 128;
        y[i] = pr[c] + bp[c];
        sum += y[i];
        sq  += y[i] * y[i];
    }
    #pragma unroll
    for (int o = 16; o; o >>= 1) {
        sum += __shfl_xor_sync(0xFFFFFFFFu, sum, o);
        sq  += __shfl_xor_sync(0xFFFFFFFFu, sq,  o);
    }
    __shared__ float s1[4], s2[4];
    int wid = tid >> 5, lane = tid & 31;
    if (lane == 0) { s1[wid] = sum; s2[wid] = sq; }
    __syncthreads();
    float tot  = s1[0] + s1[1] + s1[2] + s1[3];
    float totq = s2[0] + s2[1] + s2[2] + s2[3];

    float mu  = tot * (1.0f / C);
    float var = totq * (1.0f / C) - mu * mu;
    float rs  = rsqrtf(var + 1e-5f);
    float gm  = gamma[0];

    #pragma unroll
    for (int i = 0; i < 4; i++) {
        int c = tid + i * 128;
        float ln = (y[i] - mu) * rs * w[c] + bb[c];
        out[(size_t)row * C + c] = x[(size_t)row * C + c] + gm * ln;
    }
}

// ---------------- launch ----------------------------------------------------
extern "C" void kernel_launch(void* const* d_in, const int* in_sizes, int n_in,
                              void* d_out, int out_size)
{
    const float* x     = (const float*)d_in[0];
    const float* mask  = (const float*)d_in[1];
    const float* Wq    = (const float*)d_in[2];
    const float* Wk    = (const float*)d_in[3];
    const float* Wv    = (const float*)d_in[4];
    const float* Wp    = (const float*)d_in[5];
    const float* bp    = (const float*)d_in[6];
    const float* lnw   = (const float*)d_in[7];
    const float* lnb   = (const float*)d_in[8];
    const float* gamma = (const float*)d_in[9];
    float* out = (float*)d_out;

    float *qkvp, *op, *pp;
    cudaGetSymbolAddress((void**)&qkvp, g_qkv);
    cudaGetSymbolAddress((void**)&op, g_o);
    cudaGetSymbolAddress((void**)&pp, g_p);

    // 1) fused QKV projection (fp32 + bf16 k/v side-copy)
    gemm_tf32_v2<<<dim3(C / GN, M_TOT / GM, 3), 256>>>(
        x, Wq, Wk, Wv, qkvp, QKVC, 512, C);

    // 2) mask compression
    build_csr<<<E / 4, 128>>>(mask);

    // 3) per-(b,h) V column sums (fp32-exact)
    vsum_kernel<<<Bsz * H, 512>>>();

    // 4) sparse masked attention: bf16 gather, 8-ch threads
    attn_sparse5<<<E, 128>>>();

    // 5) output projection
    gemm_tf32_v2<<<dim3(C / GN, M_TOT / GM, 1), 256>>>(
        op, Wp, Wp, Wp, pp, C, 0, C);

    // 6) bias + LN + residual
    ln_residual<<<M_TOT, 128>>>(x, bp, lnw, lnb, gamma, out);
}

// round 7
// speedup vs baseline: 5.1371x; 1.5449x over previous
#include <cuda_runtime.h>
#include <cuda_fp16.h>

// Problem constants
#define Bsz 2
#define E 2048
#define C 512
#define H 8
#define D 64
#define M_TOT (Bsz * E)       // 4096
#define CAP 320               // per-row nnz capacity (mean ~102)
#define QC 1536               // fused q|k|v half row length

// ---------------- scratch (device globals; no allocation) ----------------
__device__ __half  g_x16[M_TOT * C];        // x in fp16
__device__ __half  g_w16[4 * C * C];        // Wq|Wk|Wv|Wp in fp16
__device__ __half  g_qkv16[M_TOT * QC];     // [row][ q | k | v ] fp16
__device__ __half  g_o16[M_TOT * C];        // attention output, fp16
__device__ float   g_p[M_TOT * C];          // proj output, fp32
__device__ int     g_cnt[E];
__device__ float2  g_pair[E * CAP];         // (rowoffset-as-bits, maskval), sorted
__device__ float   g_vsum[Bsz * C];

// ---------------- fp32 -> fp16 input conversion ---------------------------
__global__ __launch_bounds__(256) void conv_to_half(
    const float* __restrict__ x,
    const float* __restrict__ Wq, const float* __restrict__ Wk,
    const float* __restrict__ Wv, const float* __restrict__ Wp)
{
    int idx = (blockIdx.x * 256 + threadIdx.x) * 4;   // float4 granularity
    const int NX = M_TOT * C;                          // 2^21
    const float* src;
    __half* dst;
    if (idx < NX) {
        src = x + idx;
        dst = g_x16 + idx;
    } else {
        int j = idx - NX;                              // [0, 2^20)
        int region = j >> 18;
        int off = j & ((C * C) - 1);
        src = (region == 0 ? Wq : region == 1 ? Wk : region == 2 ? Wv : Wp) + off;
        dst = g_w16 + j;
    }
    float4 f = *reinterpret_cast<const float4*>(src);
    __half2 h0 = __floats2half2_rn(f.x, f.y);
    __half2 h1 = __floats2half2_rn(f.z, f.w);
    *reinterpret_cast<__half2*>(dst)     = h0;
    *reinterpret_cast<__half2*>(dst + 2) = h1;
}

// =============== fp16 tensor-core GEMM ====================================
// C[m, coloff+n] = sum_k A[m,k]*B[n,k].  128x128x32 tiles, double-buffered,
// 256 threads = 8 warps (2m x 4n), warp tile 64x32, mma m16n8k16 f16->f32.
#define GM 128
#define GN 128
#define GKH 32     // k-halves per tile
#define SAH 40     // padded row stride in halves (80B, 16B-mult, conflict-free frags)

__device__ __forceinline__ void mma_f16(float* c, const unsigned* a, const unsigned* b) {
    asm volatile(
        "mma.sync.aligned.m16n8k16.row.col.f32.f16.f16.f32 "
        "{%0,%1,%2,%3}, {%4,%5,%6,%7}, {%8,%9}, {%0,%1,%2,%3};\n"
        : "+f"(c[0]), "+f"(c[1]), "+f"(c[2]), "+f"(c[3])
        : "r"(a[0]), "r"(a[1]), "r"(a[2]), "r"(a[3]), "r"(b[0]), "r"(b[1]));
}

template <bool HALF_OUT>
__global__ __launch_bounds__(256) void gemm_f16(
    const __half* __restrict__ A,
    const __half* __restrict__ B0, const __half* __restrict__ B1,
    const __half* __restrict__ B2,
    void* __restrict__ Cout, int ldc, int coloff_mul)
{
    int z = blockIdx.z;
    const __half* Bm = (z == 0) ? B0 : (z == 1 ? B1 : B2);
    int coloff = z * coloff_mul;

    __shared__ __align__(16) __half As[2][GM][SAH];
    __shared__ __align__(16) __half Bs[2][GN][SAH];

    int tid  = threadIdx.x;
    int lane = tid & 31;
    int warp = tid >> 5;
    int m0 = blockIdx.y * GM;
    int n0 = blockIdx.x * GN;

    // loaders: 2 threads per row, 16 consecutive halves (2 x uint4) each
    int lr = tid >> 1;
    int lc = (tid & 1) * 16;
    const __half* Ag = A  + (size_t)(m0 + lr) * C + lc;
    const __half* Bg = Bm + (size_t)(n0 + lr) * C + lc;

    int m_base = (warp >> 2) * 64;
    int n_base = (warp & 3) * 32;
    int lrow = lane >> 2;          // 0..7
    int lcol = lane & 3;           // 0..3

    float acc[4][4][4];
    #pragma unroll
    for (int mi = 0; mi < 4; mi++)
        #pragma unroll
        for (int ni = 0; ni < 4; ni++)
            #pragma unroll
            for (int r = 0; r < 4; r++) acc[mi][ni][r] = 0.0f;

    const int nt = C / GKH;   // 16

    uint4 pa0, pa1, pb0, pb1;
    pa0 = *reinterpret_cast<const uint4*>(Ag);
    pa1 = *reinterpret_cast<const uint4*>(Ag + 8);
    pb0 = *reinterpret_cast<const uint4*>(Bg);
    pb1 = *reinterpret_cast<const uint4*>(Bg + 8);

    *reinterpret_cast<uint4*>(&As[0][lr][lc])     = pa0;
    *reinterpret_cast<uint4*>(&As[0][lr][lc + 8]) = pa1;
    *reinterpret_cast<uint4*>(&Bs[0][lr][lc])     = pb0;
    *reinterpret_cast<uint4*>(&Bs[0][lr][lc + 8]) = pb1;
    __syncthreads();

    for (int kt = 0; kt < nt; kt++) {
        int cur = kt & 1;
        bool more = (kt + 1) < nt;
        if (more) {
            const __half* Ap = Ag + (kt + 1) * GKH;
            const __half* Bp = Bg + (kt + 1) * GKH;
            pa0 = *reinterpret_cast<const uint4*>(Ap);
            pa1 = *reinterpret_cast<const uint4*>(Ap + 8);
            pb0 = *reinterpret_cast<const uint4*>(Bp);
            pb1 = *reinterpret_cast<const uint4*>(Bp + 8);
        }

        #pragma unroll
        for (int ks = 0; ks < 2; ks++) {
            int kc = ks * 16 + lcol * 2;
            unsigned afr[4][4];
            #pragma unroll
            for (int mi = 0; mi < 4; mi++) {
                int row = m_base + mi * 16 + lrow;
                afr[mi][0] = *reinterpret_cast<const unsigned*>(&As[cur][row][kc]);
                afr[mi][1] = *reinterpret_cast<const unsigned*>(&As[cur][row + 8][kc]);
                afr[mi][2] = *reinterpret_cast<const unsigned*>(&As[cur][row][kc + 8]);
                afr[mi][3] = *reinterpret_cast<const unsigned*>(&As[cur][row + 8][kc + 8]);
            }
            unsigned bfr[4][2];
            #pragma unroll
            for (int ni = 0; ni < 4; ni++) {
                int nn = n_base + ni * 8 + lrow;
                bfr[ni][0] = *reinterpret_cast<const unsigned*>(&Bs[cur][nn][kc]);
                bfr[ni][1] = *reinterpret_cast<const unsigned*>(&Bs[cur][nn][kc + 8]);
            }
            #pragma unroll
            for (int mi = 0; mi < 4; mi++)
                #pragma unroll
                for (int ni = 0; ni < 4; ni++)
                    mma_f16(acc[mi][ni], afr[mi], bfr[ni]);
        }

        if (more) {
            int nxt = cur ^ 1;
            *reinterpret_cast<uint4*>(&As[nxt][lr][lc])     = pa0;
            *reinterpret_cast<uint4*>(&As[nxt][lr][lc + 8]) = pa1;
            *reinterpret_cast<uint4*>(&Bs[nxt][lr][lc])     = pb0;
            *reinterpret_cast<uint4*>(&Bs[nxt][lr][lc + 8]) = pb1;
            __syncthreads();
        }
    }

    // epilogue
    #pragma unroll
    for (int mi = 0; mi < 4; mi++) {
        #pragma unroll
        for (int ni = 0; ni < 4; ni++) {
            int r  = m0 + m_base + mi * 16 + lrow;
            int cc = coloff + n0 + n_base + ni * 8 + lcol * 2;
            if (HALF_OUT) {
                __half* Ch = (__half*)Cout;
                *reinterpret_cast<__half2*>(Ch + (size_t)r * ldc + cc) =
                    __floats2half2_rn(acc[mi][ni][0], acc[mi][ni][1]);
                *reinterpret_cast<__half2*>(Ch + (size_t)(r + 8) * ldc + cc) =
                    __floats2half2_rn(acc[mi][ni][2], acc[mi][ni][3]);
            } else {
                float* Cf = (float*)Cout;
                *reinterpret_cast<float2*>(Cf + (size_t)r * ldc + cc) =
                    make_float2(acc[mi][ni][0], acc[mi][ni][1]);
                *reinterpret_cast<float2*>(Cf + (size_t)(r + 8) * ldc + cc) =
                    make_float2(acc[mi][ni][2], acc[mi][ni][3]);
            }
        }
    }
}

// ---------------- mask -> per-row compressed (rowoff,val) pairs ------------
__global__ __launch_bounds__(128) void build_csr(const float* __restrict__ mask)
{
    int row  = blockIdx.x * 4 + (threadIdx.x >> 5);
    int lane = threadIdx.x & 31;
    if (row >= E) return;

    int cnt = 0;
    const float* mrow = mask + (size_t)row * E;
    for (int j0 = 0; j0 < E; j0 += 32) {
        float v = mrow[j0 + lane];
        unsigned bal = __ballot_sync(0xFFFFFFFFu, v != 0.0f);
        if (v != 0.0f) {
            int off = cnt + __popc(bal & ((1u << lane) - 1u));
            if (off < CAP) {
                // store precomputed half-offset of that key row (idx * QC)
                g_pair[row * CAP + off] =
                    make_float2(__int_as_float((j0 + lane) * QC), v);
            }
        }
        cnt += __popc(bal);
    }
    if (lane == 0) g_cnt[row] = (cnt > CAP) ? CAP : cnt;
}

// ---------------- vsum[b][c] = sum_e v16[b,e,c]  (fp32 accum) --------------
__global__ __launch_bounds__(512) void vsum_kernel()
{
    int bh = blockIdx.x;           // 0..15
    int b = bh >> 3, h = bh & 7;
    int d2 = threadIdx.x & 31;     // half2 channel pair 0..31
    int sl = threadIdx.x >> 5;     // 0..15
    const __half* vb = g_qkv16 + (size_t)b * E * QC + 1024 + h * D + d2 * 2;
    float sx = 0.0f, sy = 0.0f;
    for (int e = sl; e < E; e += 16) {
        float2 f = __half22float2(*reinterpret_cast<const __half2*>(vb + (size_t)e * QC));
        sx += f.x; sy += f.y;
    }
    __shared__ float2 red[16][32];
    red[sl][d2] = make_float2(sx, sy);
    __syncthreads();
    if (sl == 0) {
        float tx = 0.0f, ty = 0.0f;
        #pragma unroll
        for (int i = 0; i < 16; i++) { tx += red[i][d2].x; ty += red[i][d2].y; }
        g_vsum[b * C + h * D + d2 * 2]     = tx;
        g_vsum[b * C + h * D + d2 * 2 + 1] = ty;
    }
}

// ---------------- sparse masked attention v6: fp16 gather ------------------
// Block (128 thr) per query q: 2 batches x 64 threads; thread owns 8 channels.
__device__ __forceinline__ void h8_to_f(uint4 r, float* f) {
    float2 a = __half22float2(*reinterpret_cast<__half2*>(&r.x));
    float2 b = __half22float2(*reinterpret_cast<__half2*>(&r.y));
    float2 c = __half22float2(*reinterpret_cast<__half2*>(&r.z));
    float2 d = __half22float2(*reinterpret_cast<__half2*>(&r.w));
    f[0] = a.x; f[1] = a.y; f[2] = b.x; f[3] = b.y;
    f[4] = c.x; f[5] = c.y; f[6] = d.x; f[7] = d.y;
}

__global__ __launch_bounds__(128) void attn_sparse6()
{
    __shared__ float2 sp[CAP];

    int q   = blockIdx.x;
    int tid = threadIdx.x;        // 0..127
    int bb  = tid >> 6;           // batch 0/1
    int t   = tid & 63;
    int c0  = t * 8;              // channel start (head = c0/64)

    int n    = g_cnt[q];
    int npad = (n + 3) & ~3;
    for (int i = tid; i < npad; i += 128)
        sp[i] = (i < n) ? g_pair[q * CAP + i] : make_float2(__int_as_float(0), 0.0f);
    __syncthreads();

    const __half* kvb = g_qkv16 + (size_t)bb * E * QC;

    float qv[8];
    {
        uint4 qr = *reinterpret_cast<const uint4*>(kvb + (size_t)q * QC + c0);
        h8_to_f(qr, qv);
    }

    float acc[8];
    {
        float4 a = *reinterpret_cast<const float4*>(g_vsum + bb * C + c0);
        float4 b = *reinterpret_cast<const float4*>(g_vsum + bb * C + c0 + 4);
        acc[0] = 0.5f * a.x; acc[1] = 0.5f * a.y; acc[2] = 0.5f * a.z; acc[3] = 0.5f * a.w;
        acc[4] = 0.5f * b.x; acc[5] = 0.5f * b.y; acc[6] = 0.5f * b.z; acc[7] = 0.5f * b.w;
    }

    const __half* kb = kvb + 512 + c0;   // + rowoff -> k row; +512 more -> v

    for (int i = 0; i < npad; i += 4) {
        float2 pr0 = sp[i], pr1 = sp[i + 1], pr2 = sp[i + 2], pr3 = sp[i + 3];
        int o0 = __float_as_int(pr0.x);
        int o1 = __float_as_int(pr1.x);
        int o2 = __float_as_int(pr2.x);
        int o3 = __float_as_int(pr3.x);

        const __half* r0 = kb + o0;
        const __half* r1 = kb + o1;
        const __half* r2 = kb + o2;
        const __half* r3 = kb + o3;

        uint4 kr0 = *reinterpret_cast<const uint4*>(r0);
        uint4 kr1 = *reinterpret_cast<const uint4*>(r1);
        uint4 kr2 = *reinterpret_cast<const uint4*>(r2);
        uint4 kr3 = *reinterpret_cast<const uint4*>(r3);
        uint4 vr0 = *reinterpret_cast<const uint4*>(r0 + 512);
        uint4 vr1 = *reinterpret_cast<const uint4*>(r1 + 512);
        uint4 vr2 = *reinterpret_cast<const uint4*>(r2 + 512);
        uint4 vr3 = *reinterpret_cast<const uint4*>(r3 + 512);

        float k0[8], k1[8], k2[8], k3[8];
        h8_to_f(kr0, k0); h8_to_f(kr1, k1); h8_to_f(kr2, k2); h8_to_f(kr3, k3);

        float p0 = 0.f, p1 = 0.f, p2 = 0.f, p3 = 0.f;
        #pragma unroll
        for (int j = 0; j < 8; j++) {
            p0 += qv[j] * k0[j];
            p1 += qv[j] * k1[j];
            p2 += qv[j] * k2[j];
            p3 += qv[j] * k3[j];
        }
        #pragma unroll
        for (int o = 1; o < 8; o <<= 1) {
            p0 += __shfl_xor_sync(0xFFFFFFFFu, p0, o, 8);
            p1 += __shfl_xor_sync(0xFFFFFFFFu, p1, o, 8);
            p2 += __shfl_xor_sync(0xFFFFFFFFu, p2, o, 8);
            p3 += __shfl_xor_sync(0xFFFFFFFFu, p3, o, 8);
        }

        float s0 = 0.5f * pr0.y * p0;
        float s1 = 0.5f * pr1.y * p1;
        float s2 = 0.5f * pr2.y * p2;
        float s3 = 0.5f * pr3.y * p3;

        float v0[8], v1[8], v2[8], v3[8];
        h8_to_f(vr0, v0); h8_to_f(vr1, v1); h8_to_f(vr2, v2); h8_to_f(vr3, v3);

        #pragma unroll
        for (int j = 0; j < 8; j++)
            acc[j] += s0 * v0[j] + s1 * v1[j] + s2 * v2[j] + s3 * v3[j];
    }

    // pack to fp16 and store 16B
    uint4 outp;
    __half2* hp = reinterpret_cast<__half2*>(&outp);
    hp[0] = __floats2half2_rn(acc[0], acc[1]);
    hp[1] = __floats2half2_rn(acc[2], acc[3]);
    hp[2] = __floats2half2_rn(acc[4], acc[5]);
    hp[3] = __floats2half2_rn(acc[6], acc[7]);
    *reinterpret_cast<uint4*>(g_o16 + ((size_t)(bb * E + q)) * C + c0) = outp;
}

// ---------------- bias + LayerNorm + residual ------------------------------
__global__ __launch_bounds__(128) void ln_residual(
    const float* __restrict__ x,  const float* __restrict__ bp,
    const float* __restrict__ w,  const float* __restrict__ bb,
    const float* __restrict__ gamma, float* __restrict__ out)
{
    int row = blockIdx.x;          // 0..4095
    int tid = threadIdx.x;         // 128
    const float* pr = g_p + (size_t)row * C;

    float y[4];
    float sum = 0.0f, sq = 0.0f;
    #pragma unroll
    for (int i = 0; i < 4; i++) {
        int c = tid + i * 128;
        y[i] = pr[c] + bp[c];
        sum += y[i];
        sq  += y[i] * y[i];
    }
    #pragma unroll
    for (int o = 16; o; o >>= 1) {
        sum += __shfl_xor_sync(0xFFFFFFFFu, sum, o);
        sq  += __shfl_xor_sync(0xFFFFFFFFu, sq,  o);
    }
    __shared__ float s1[4], s2[4];
    int wid = tid >> 5, lane = tid & 31;
    if (lane == 0) { s1[wid] = sum; s2[wid] = sq; }
    __syncthreads();
    float tot  = s1[0] + s1[1] + s1[2] + s1[3];
    float totq = s2[0] + s2[1] + s2[2] + s2[3];

    float mu  = tot * (1.0f / C);
    float var = totq * (1.0f / C) - mu * mu;
    float rs  = rsqrtf(var + 1e-5f);
    float gm  = gamma[0];

    #pragma unroll
    for (int i = 0; i < 4; i++) {
        int c = tid + i * 128;
        float ln = (y[i] - mu) * rs * w[c] + bb[c];
        out[(size_t)row * C + c] = x[(size_t)row * C + c] + gm * ln;
    }
}

// ---------------- launch ----------------------------------------------------
extern "C" void kernel_launch(void* const* d_in, const int* in_sizes, int n_in,
                              void* d_out, int out_size)
{
    const float* x     = (const float*)d_in[0];
    const float* mask  = (const float*)d_in[1];
    const float* Wq    = (const float*)d_in[2];
    const float* Wk    = (const float*)d_in[3];
    const float* Wv    = (const float*)d_in[4];
    const float* Wp    = (const float*)d_in[5];
    const float* bp    = (const float*)d_in[6];
    const float* lnw   = (const float*)d_in[7];
    const float* lnb   = (const float*)d_in[8];
    const float* gamma = (const float*)d_in[9];
    float* out = (float*)d_out;

    __half *x16p, *w16p, *qkv16p, *o16p;
    float *pp;
    cudaGetSymbolAddress((void**)&x16p, g_x16);
    cudaGetSymbolAddress((void**)&w16p, g_w16);
    cudaGetSymbolAddress((void**)&qkv16p, g_qkv16);
    cudaGetSymbolAddress((void**)&o16p, g_o16);
    cudaGetSymbolAddress((void**)&pp, g_p);

    const int NCONV = (M_TOT * C + 4 * C * C) / 4 / 256;   // 3072 blocks

    // 0) convert x and weights to fp16
    conv_to_half<<<NCONV, 256>>>(x, Wq, Wk, Wv, Wp);

    // 1) fused QKV projection -> g_qkv16 (fp16)
    gemm_f16<true><<<dim3(C / GN, M_TOT / GM, 3), 256>>>(
        x16p, w16p, w16p + C * C, w16p + 2 * C * C, qkv16p, QC, 512);

    // 2) mask compression
    build_csr<<<E / 4, 128>>>(mask);

    // 3) per-(b,h) V column sums
    vsum_kernel<<<Bsz * H, 512>>>();

    // 4) sparse masked attention (fp16 gather) -> g_o16
    attn_sparse6<<<E, 128>>>();

    // 5) output projection -> g_p (fp32)
    gemm_f16<false><<<dim3(C / GN, M_TOT / GM, 1), 256>>>(
        o16p, w16p + 3 * C * C, w16p + 3 * C * C, w16p + 3 * C * C, pp, C, 0);

    // 6) bias + LN + residual
    ln_residual<<<M_TOT, 128>>>(x, bp, lnw, lnb, gamma, out);
}

// round 8
// speedup vs baseline: 5.1853x; 1.0094x over previous
#include <cuda_runtime.h>
#include <cuda_fp16.h>

// Problem constants
#define Bsz 2
#define E 2048
#define C 512
#define H 8
#define D 64
#define M_TOT (Bsz * E)       // 4096
#define CAP 320               // per-row nnz capacity (mean ~102)
#define QC 1536               // fused q|k|v half row length

// ---------------- scratch (device globals; no allocation) ----------------
__device__ __half  g_x16[M_TOT * C];        // x in fp16
__device__ __half  g_w16[4 * C * C];        // Wq|Wk|Wv|Wp in fp16
__device__ __half  g_qkv16[M_TOT * QC];     // [row][ q | k | v ] fp16
__device__ __half  g_o16[M_TOT * C];        // attention output, fp16
__device__ float   g_p[M_TOT * C];          // proj output, fp32
__device__ int     g_cnt[E];
__device__ float2  g_pair[E * CAP];         // (rowoffset-as-bits, maskval), sorted
__device__ float   g_vsum[Bsz * C];

// ---------------- fp32 -> fp16 input conversion ---------------------------
__global__ __launch_bounds__(256) void conv_to_half(
    const float* __restrict__ x,
    const float* __restrict__ Wq, const float* __restrict__ Wk,
    const float* __restrict__ Wv, const float* __restrict__ Wp)
{
    int idx = (blockIdx.x * 256 + threadIdx.x) * 4;   // float4 granularity
    const int NX = M_TOT * C;                          // 2^21
    const float* src;
    __half* dst;
    if (idx < NX) {
        src = x + idx;
        dst = g_x16 + idx;
    } else {
        int j = idx - NX;                              // [0, 2^20)
        int region = j >> 18;
        int off = j & ((C * C) - 1);
        src = (region == 0 ? Wq : region == 1 ? Wk : region == 2 ? Wv : Wp) + off;
        dst = g_w16 + j;
    }
    float4 f = *reinterpret_cast<const float4*>(src);
    __half2 h0 = __floats2half2_rn(f.x, f.y);
    __half2 h1 = __floats2half2_rn(f.z, f.w);
    *reinterpret_cast<__half2*>(dst)     = h0;
    *reinterpret_cast<__half2*>(dst + 2) = h1;
}

// =============== fp16 tensor-core GEMM ====================================
// C[m, coloff+n] = sum_k A[m,k]*B[n,k].  128x128x32 tiles, double-buffered,
// 256 threads = 8 warps (2m x 4n), warp tile 64x32, mma m16n8k16 f16->f32.
#define GM 128
#define GN 128
#define GKH 32     // k-halves per tile
#define SAH 40     // padded row stride in halves

__device__ __forceinline__ void mma_f16(float* c, const unsigned* a, const unsigned* b) {
    asm volatile(
        "mma.sync.aligned.m16n8k16.row.col.f32.f16.f16.f32 "
        "{%0,%1,%2,%3}, {%4,%5,%6,%7}, {%8,%9}, {%0,%1,%2,%3};\n"
        : "+f"(c[0]), "+f"(c[1]), "+f"(c[2]), "+f"(c[3])
        : "r"(a[0]), "r"(a[1]), "r"(a[2]), "r"(a[3]), "r"(b[0]), "r"(b[1]));
}

template <bool HALF_OUT>
__global__ __launch_bounds__(256) void gemm_f16(
    const __half* __restrict__ A,
    const __half* __restrict__ B0, const __half* __restrict__ B1,
    const __half* __restrict__ B2,
    void* __restrict__ Cout, int ldc, int coloff_mul)
{
    int z = blockIdx.z;
    const __half* Bm = (z == 0) ? B0 : (z == 1 ? B1 : B2);
    int coloff = z * coloff_mul;

    __shared__ __align__(16) __half As[2][GM][SAH];
    __shared__ __align__(16) __half Bs[2][GN][SAH];

    int tid  = threadIdx.x;
    int lane = tid & 31;
    int warp = tid >> 5;
    int m0 = blockIdx.y * GM;
    int n0 = blockIdx.x * GN;

    int lr = tid >> 1;
    int lc = (tid & 1) * 16;
    const __half* Ag = A  + (size_t)(m0 + lr) * C + lc;
    const __half* Bg = Bm + (size_t)(n0 + lr) * C + lc;

    int m_base = (warp >> 2) * 64;
    int n_base = (warp & 3) * 32;
    int lrow = lane >> 2;
    int lcol = lane & 3;

    float acc[4][4][4];
    #pragma unroll
    for (int mi = 0; mi < 4; mi++)
        #pragma unroll
        for (int ni = 0; ni < 4; ni++)
            #pragma unroll
            for (int r = 0; r < 4; r++) acc[mi][ni][r] = 0.0f;

    const int nt = C / GKH;   // 16

    uint4 pa0, pa1, pb0, pb1;
    pa0 = *reinterpret_cast<const uint4*>(Ag);
    pa1 = *reinterpret_cast<const uint4*>(Ag + 8);
    pb0 = *reinterpret_cast<const uint4*>(Bg);
    pb1 = *reinterpret_cast<const uint4*>(Bg + 8);

    *reinterpret_cast<uint4*>(&As[0][lr][lc])     = pa0;
    *reinterpret_cast<uint4*>(&As[0][lr][lc + 8]) = pa1;
    *reinterpret_cast<uint4*>(&Bs[0][lr][lc])     = pb0;
    *reinterpret_cast<uint4*>(&Bs[0][lr][lc + 8]) = pb1;
    __syncthreads();

    for (int kt = 0; kt < nt; kt++) {
        int cur = kt & 1;
        bool more = (kt + 1) < nt;
        if (more) {
            const __half* Ap = Ag + (kt + 1) * GKH;
            const __half* Bp = Bg + (kt + 1) * GKH;
            pa0 = *reinterpret_cast<const uint4*>(Ap);
            pa1 = *reinterpret_cast<const uint4*>(Ap + 8);
            pb0 = *reinterpret_cast<const uint4*>(Bp);
            pb1 = *reinterpret_cast<const uint4*>(Bp + 8);
        }

        #pragma unroll
        for (int ks = 0; ks < 2; ks++) {
            int kc = ks * 16 + lcol * 2;
            unsigned afr[4][4];
            #pragma unroll
            for (int mi = 0; mi < 4; mi++) {
                int row = m_base + mi * 16 + lrow;
                afr[mi][0] = *reinterpret_cast<const unsigned*>(&As[cur][row][kc]);
                afr[mi][1] = *reinterpret_cast<const unsigned*>(&As[cur][row + 8][kc]);
                afr[mi][2] = *reinterpret_cast<const unsigned*>(&As[cur][row][kc + 8]);
                afr[mi][3] = *reinterpret_cast<const unsigned*>(&As[cur][row + 8][kc + 8]);
            }
            unsigned bfr[4][2];
            #pragma unroll
            for (int ni = 0; ni < 4; ni++) {
                int nn = n_base + ni * 8 + lrow;
                bfr[ni][0] = *reinterpret_cast<const unsigned*>(&Bs[cur][nn][kc]);
                bfr[ni][1] = *reinterpret_cast<const unsigned*>(&Bs[cur][nn][kc + 8]);
            }
            #pragma unroll
            for (int mi = 0; mi < 4; mi++)
                #pragma unroll
                for (int ni = 0; ni < 4; ni++)
                    mma_f16(acc[mi][ni], afr[mi], bfr[ni]);
        }

        if (more) {
            int nxt = cur ^ 1;
            *reinterpret_cast<uint4*>(&As[nxt][lr][lc])     = pa0;
            *reinterpret_cast<uint4*>(&As[nxt][lr][lc + 8]) = pa1;
            *reinterpret_cast<uint4*>(&Bs[nxt][lr][lc])     = pb0;
            *reinterpret_cast<uint4*>(&Bs[nxt][lr][lc + 8]) = pb1;
            __syncthreads();
        }
    }

    #pragma unroll
    for (int mi = 0; mi < 4; mi++) {
        #pragma unroll
        for (int ni = 0; ni < 4; ni++) {
            int r  = m0 + m_base + mi * 16 + lrow;
            int cc = coloff + n0 + n_base + ni * 8 + lcol * 2;
            if (HALF_OUT) {
                __half* Ch = (__half*)Cout;
                *reinterpret_cast<__half2*>(Ch + (size_t)r * ldc + cc) =
                    __floats2half2_rn(acc[mi][ni][0], acc[mi][ni][1]);
                *reinterpret_cast<__half2*>(Ch + (size_t)(r + 8) * ldc + cc) =
                    __floats2half2_rn(acc[mi][ni][2], acc[mi][ni][3]);
            } else {
                float* Cf = (float*)Cout;
                *reinterpret_cast<float2*>(Cf + (size_t)r * ldc + cc) =
                    make_float2(acc[mi][ni][0], acc[mi][ni][1]);
                *reinterpret_cast<float2*>(Cf + (size_t)(r + 8) * ldc + cc) =
                    make_float2(acc[mi][ni][2], acc[mi][ni][3]);
            }
        }
    }
}

// ---------------- mask -> per-row compressed (rowoff,val) pairs ------------
// Warp per row; float4 loads (128 cols/iter); order-preserving warp scan.
__global__ __launch_bounds__(128) void build_csr(const float* __restrict__ mask)
{
    int row  = blockIdx.x * 4 + (threadIdx.x >> 5);
    int lane = threadIdx.x & 31;

    int cnt = 0;
    const float* mrow = mask + (size_t)row * E;
    float2* prow = g_pair + row * CAP;

    for (int j0 = 0; j0 < E; j0 += 128) {
        float4 v = *reinterpret_cast<const float4*>(mrow + j0 + lane * 4);
        int c4 = (v.x != 0.0f) + (v.y != 0.0f) + (v.z != 0.0f) + (v.w != 0.0f);
        // inclusive scan of c4 across the warp
        int inc = c4;
        #pragma unroll
        for (int o = 1; o < 32; o <<= 1) {
            int t = __shfl_up_sync(0xFFFFFFFFu, inc, o);
            if (lane >= o) inc += t;
        }
        int base = cnt + inc - c4;
        int tot  = __shfl_sync(0xFFFFFFFFu, inc, 31);
        int jb   = j0 + lane * 4;
        int w = 0;
        if (v.x != 0.0f) { if (base + w < CAP) prow[base + w] = make_float2(__int_as_float((jb + 0) * QC), v.x); w++; }
        if (v.y != 0.0f) { if (base + w < CAP) prow[base + w] = make_float2(__int_as_float((jb + 1) * QC), v.y); w++; }
        if (v.z != 0.0f) { if (base + w < CAP) prow[base + w] = make_float2(__int_as_float((jb + 2) * QC), v.z); w++; }
        if (v.w != 0.0f) { if (base + w < CAP) prow[base + w] = make_float2(__int_as_float((jb + 3) * QC), v.w); w++; }
        cnt += tot;
    }
    if (lane == 0) g_cnt[row] = (cnt > CAP) ? CAP : cnt;
}

// ---------------- vsum: zero + 128-block partial sums ----------------------
__global__ __launch_bounds__(256) void zero_vsum()
{
    int i = threadIdx.x * 4;
    *reinterpret_cast<float4*>(g_vsum + i) = make_float4(0.f, 0.f, 0.f, 0.f);
}

__global__ __launch_bounds__(256) void vsum_part()
{
    int bh = blockIdx.x;            // 0..15
    int ch = blockIdx.y;            // 0..7 (e-chunks of 256)
    int b = bh >> 3, h = bh & 7;
    int d2 = threadIdx.x & 31;      // half2 channel pair
    int sl = threadIdx.x >> 5;      // 0..7

    const __half* vb = g_qkv16 + (size_t)b * E * QC + 1024 + h * D + d2 * 2;
    int e0 = ch * 256;
    float sx = 0.0f, sy = 0.0f;
    #pragma unroll 4
    for (int e = e0 + sl; e < e0 + 256; e += 8) {
        float2 f = __half22float2(*reinterpret_cast<const __half2*>(vb + (size_t)e * QC));
        sx += f.x; sy += f.y;
    }
    __shared__ float2 red[8][32];
    red[sl][d2] = make_float2(sx, sy);
    __syncthreads();
    if (sl == 0) {
        float tx = 0.0f, ty = 0.0f;
        #pragma unroll
        for (int i = 0; i < 8; i++) { tx += red[i][d2].x; ty += red[i][d2].y; }
        atomicAdd(&g_vsum[b * C + h * D + d2 * 2],     tx);
        atomicAdd(&g_vsum[b * C + h * D + d2 * 2 + 1], ty);
    }
}

// ---------------- sparse masked attention v7: half2 dot --------------------
// Block (128 thr) per query q: 2 batches x 64 threads; thread owns 8 channels.
__device__ __forceinline__ void h8_to_f(uint4 r, float* f) {
    float2 a = __half22float2(*reinterpret_cast<__half2*>(&r.x));
    float2 b = __half22float2(*reinterpret_cast<__half2*>(&r.y));
    float2 c = __half22float2(*reinterpret_cast<__half2*>(&r.z));
    float2 d = __half22float2(*reinterpret_cast<__half2*>(&r.w));
    f[0] = a.x; f[1] = a.y; f[2] = b.x; f[3] = b.y;
    f[4] = c.x; f[5] = c.y; f[6] = d.x; f[7] = d.y;
}

__device__ __forceinline__ float hdot8(uint4 qr, uint4 kr) {
    const __half2* qh = reinterpret_cast<const __half2*>(&qr);
    const __half2* kh = reinterpret_cast<const __half2*>(&kr);
    __half2 p = __hmul2(qh[0], kh[0]);
    p = __hfma2(qh[1], kh[1], p);
    p = __hfma2(qh[2], kh[2], p);
    p = __hfma2(qh[3], kh[3], p);
    float2 pf = __half22float2(p);
    return pf.x + pf.y;
}

__global__ __launch_bounds__(128) void attn_sparse7()
{
    __shared__ float2 sp[CAP];

    int q   = blockIdx.x;
    int tid = threadIdx.x;        // 0..127
    int bb  = tid >> 6;           // batch 0/1
    int t   = tid & 63;
    int c0  = t * 8;              // channel start (head = c0/64)

    int n    = g_cnt[q];
    int npad = (n + 3) & ~3;
    for (int i = tid; i < npad; i += 128)
        sp[i] = (i < n) ? g_pair[q * CAP + i] : make_float2(__int_as_float(0), 0.0f);
    __syncthreads();

    const __half* kvb = g_qkv16 + (size_t)bb * E * QC;

    uint4 qr = *reinterpret_cast<const uint4*>(kvb + (size_t)q * QC + c0);

    float acc[8];
    {
        float4 a = *reinterpret_cast<const float4*>(g_vsum + bb * C + c0);
        float4 b = *reinterpret_cast<const float4*>(g_vsum + bb * C + c0 + 4);
        acc[0] = 0.5f * a.x; acc[1] = 0.5f * a.y; acc[2] = 0.5f * a.z; acc[3] = 0.5f * a.w;
        acc[4] = 0.5f * b.x; acc[5] = 0.5f * b.y; acc[6] = 0.5f * b.z; acc[7] = 0.5f * b.w;
    }

    const __half* kb = kvb + 512 + c0;   // + rowoff -> k row; +512 more -> v

    for (int i = 0; i < npad; i += 4) {
        float2 pr0 = sp[i], pr1 = sp[i + 1], pr2 = sp[i + 2], pr3 = sp[i + 3];
        const __half* r0 = kb + __float_as_int(pr0.x);
        const __half* r1 = kb + __float_as_int(pr1.x);
        const __half* r2 = kb + __float_as_int(pr2.x);
        const __half* r3 = kb + __float_as_int(pr3.x);

        uint4 kr0 = *reinterpret_cast<const uint4*>(r0);
        uint4 kr1 = *reinterpret_cast<const uint4*>(r1);
        uint4 kr2 = *reinterpret_cast<const uint4*>(r2);
        uint4 kr3 = *reinterpret_cast<const uint4*>(r3);
        uint4 vr0 = *reinterpret_cast<const uint4*>(r0 + 512);
        uint4 vr1 = *reinterpret_cast<const uint4*>(r1 + 512);
        uint4 vr2 = *reinterpret_cast<const uint4*>(r2 + 512);
        uint4 vr3 = *reinterpret_cast<const uint4*>(r3 + 512);

        float p0 = hdot8(qr, kr0);
        float p1 = hdot8(qr, kr1);
        float p2 = hdot8(qr, kr2);
        float p3 = hdot8(qr, kr3);

        #pragma unroll
        for (int o = 1; o < 8; o <<= 1) {
            p0 += __shfl_xor_sync(0xFFFFFFFFu, p0, o, 8);
            p1 += __shfl_xor_sync(0xFFFFFFFFu, p1, o, 8);
            p2 += __shfl_xor_sync(0xFFFFFFFFu, p2, o, 8);
            p3 += __shfl_xor_sync(0xFFFFFFFFu, p3, o, 8);
        }

        float s0 = 0.5f * pr0.y * p0;
        float s1 = 0.5f * pr1.y * p1;
        float s2 = 0.5f * pr2.y * p2;
        float s3 = 0.5f * pr3.y * p3;

        float v0[8], v1[8], v2[8], v3[8];
        h8_to_f(vr0, v0); h8_to_f(vr1, v1); h8_to_f(vr2, v2); h8_to_f(vr3, v3);

        #pragma unroll
        for (int j = 0; j < 8; j++)
            acc[j] += s0 * v0[j] + s1 * v1[j] + s2 * v2[j] + s3 * v3[j];
    }

    uint4 outp;
    __half2* hp = reinterpret_cast<__half2*>(&outp);
    hp[0] = __floats2half2_rn(acc[0], acc[1]);
    hp[1] = __floats2half2_rn(acc[2], acc[3]);
    hp[2] = __floats2half2_rn(acc[4], acc[5]);
    hp[3] = __floats2half2_rn(acc[6], acc[7]);
    *reinterpret_cast<uint4*>(g_o16 + ((size_t)(bb * E + q)) * C + c0) = outp;
}

// ---------------- bias + LayerNorm + residual ------------------------------
__global__ __launch_bounds__(128) void ln_residual(
    const float* __restrict__ x,  const float* __restrict__ bp,
    const float* __restrict__ w,  const float* __restrict__ bb,
    const float* __restrict__ gamma, float* __restrict__ out)
{
    int row = blockIdx.x;          // 0..4095
    int tid = threadIdx.x;         // 128
    const float* pr = g_p + (size_t)row * C;

    float y[4];
    float sum = 0.0f, sq = 0.0f;
    #pragma unroll
    for (int i = 0; i < 4; i++) {
        int c = tid + i * 128;
        y[i] = pr[c] + bp[c];
        sum += y[i];
        sq  += y[i] * y[i];
    }
    #pragma unroll
    for (int o = 16; o; o >>= 1) {
        sum += __shfl_xor_sync(0xFFFFFFFFu, sum, o);
        sq  += __shfl_xor_sync(0xFFFFFFFFu, sq,  o);
    }
    __shared__ float s1[4], s2[4];
    int wid = tid >> 5, lane = tid & 31;
    if (lane == 0) { s1[wid] = sum; s2[wid] = sq; }
    __syncthreads();
    float tot  = s1[0] + s1[1] + s1[2] + s1[3];
    float totq = s2[0] + s2[1] + s2[2] + s2[3];

    float mu  = tot * (1.0f / C);
    float var = totq * (1.0f / C) - mu * mu;
    float rs  = rsqrtf(var + 1e-5f);
    float gm  = gamma[0];

    #pragma unroll
    for (int i = 0; i < 4; i++) {
        int c = tid + i * 128;
        float ln = (y[i] - mu) * rs * w[c] + bb[c];
        out[(size_t)row * C + c] = x[(size_t)row * C + c] + gm * ln;
    }
}

// ---------------- launch ----------------------------------------------------
extern "C" void kernel_launch(void* const* d_in, const int* in_sizes, int n_in,
                              void* d_out, int out_size)
{
    const float* x     = (const float*)d_in[0];
    const float* mask  = (const float*)d_in[1];
    const float* Wq    = (const float*)d_in[2];
    const float* Wk    = (const float*)d_in[3];
    const float* Wv    = (const float*)d_in[4];
    const float* Wp    = (const float*)d_in[5];
    const float* bp    = (const float*)d_in[6];
    const float* lnw   = (const float*)d_in[7];
    const float* lnb   = (const float*)d_in[8];
    const float* gamma = (const float*)d_in[9];
    float* out = (float*)d_out;

    __half *x16p, *w16p, *qkv16p, *o16p;
    float *pp;
    cudaGetSymbolAddress((void**)&x16p, g_x16);
    cudaGetSymbolAddress((void**)&w16p, g_w16);
    cudaGetSymbolAddress((void**)&qkv16p, g_qkv16);
    cudaGetSymbolAddress((void**)&o16p, g_o16);
    cudaGetSymbolAddress((void**)&pp, g_p);

    const int NCONV = (M_TOT * C + 4 * C * C) / 4 / 256;   // 3072 blocks

    // 0) convert x and weights to fp16; zero vsum accumulators
    conv_to_half<<<NCONV, 256>>>(x, Wq, Wk, Wv, Wp);
    zero_vsum<<<1, 256>>>();

    // 1) fused QKV projection -> g_qkv16 (fp16)
    gemm_f16<true><<<dim3(C / GN, M_TOT / GM, 3), 256>>>(
        x16p, w16p, w16p + C * C, w16p + 2 * C * C, qkv16p, QC, 512);

    // 2) mask compression
    build_csr<<<E / 4, 128>>>(mask);

    // 3) per-(b,h) V column sums (partial-sum blocks + atomics)
    vsum_part<<<dim3(Bsz * H, 8), 256>>>();

    // 4) sparse masked attention (fp16 gather, half2 dot) -> g_o16
    attn_sparse7<<<E, 128>>>();

    // 5) output projection -> g_p (fp32)
    gemm_f16<false><<<dim3(C / GN, M_TOT / GM, 1), 256>>>(
        o16p, w16p + 3 * C * C, w16p + 3 * C * C, w16p + 3 * C * C, pp, C, 0);

    // 6) bias + LN + residual
    ln_residual<<<M_TOT, 128>>>(x, bp, lnw, lnb, gamma, out);
}

// round 9
// speedup vs baseline: 5.3378x; 1.0294x over previous
#include <cuda_runtime.h>
#include <cuda_fp16.h>

// Problem constants
#define Bsz 2
#define E 2048
#define C 512
#define H 8
#define D 64
#define M_TOT (Bsz * E)       // 4096
#define CAP 320               // per-row nnz capacity (mean ~102)
#define QC 1536               // fused q|k|v half row length

// ---------------- scratch (device globals; no allocation) ----------------
__device__ __half  g_x16[M_TOT * C];        // x in fp16
__device__ __half  g_w16[4 * C * C];        // Wq|Wk|Wv|Wp in fp16
__device__ __half  g_qkv16[M_TOT * QC];     // [row][ q | k | v ] fp16
__device__ __half  g_o16[M_TOT * C];        // attention output, fp16
__device__ float   g_p[M_TOT * C];          // proj output, fp32
__device__ int     g_cnt[E];
__device__ float2  g_pair[E * CAP];         // (rowoffset-as-bits, maskval)
__device__ float   g_vsum[Bsz * C];

// ---------------- fp32 -> fp16 input conversion (+ vsum zeroing) ----------
__global__ __launch_bounds__(256) void conv_to_half(
    const float* __restrict__ x,
    const float* __restrict__ Wq, const float* __restrict__ Wk,
    const float* __restrict__ Wv, const float* __restrict__ Wp)
{
    if (blockIdx.x == 0) {   // also zero the vsum accumulator (1024 floats)
        *reinterpret_cast<float4*>(g_vsum + threadIdx.x * 4) =
            make_float4(0.f, 0.f, 0.f, 0.f);
    }
    int idx = (blockIdx.x * 256 + threadIdx.x) * 4;   // float4 granularity
    const int NX = M_TOT * C;                          // 2^21
    const float* src;
    __half* dst;
    if (idx < NX) {
        src = x + idx;
        dst = g_x16 + idx;
    } else {
        int j = idx - NX;                              // [0, 2^20)
        int region = j >> 18;
        int off = j & ((C * C) - 1);
        src = (region == 0 ? Wq : region == 1 ? Wk : region == 2 ? Wv : Wp) + off;
        dst = g_w16 + j;
    }
    float4 f = *reinterpret_cast<const float4*>(src);
    __half2 h0 = __floats2half2_rn(f.x, f.y);
    __half2 h1 = __floats2half2_rn(f.z, f.w);
    *reinterpret_cast<__half2*>(dst)     = h0;
    *reinterpret_cast<__half2*>(dst + 2) = h1;
}

// =============== fp16 tensor-core GEMM (ldmatrix frag loads) ==============
// C[m, coloff+n] = sum_k A[m,k]*B[n,k].  128x128x32 tiles, double-buffered,
// 256 threads = 8 warps (2m x 4n), warp tile 64x32, mma m16n8k16 f16->f32.
#define GM 128
#define GN 128
#define GKH 32     // k-halves per tile
#define SAH 40     // padded row stride in halves (80B -> conflict-free LDSM)

__device__ __forceinline__ void mma_f16(float* c, const unsigned* a, const unsigned* b) {
    asm volatile(
        "mma.sync.aligned.m16n8k16.row.col.f32.f16.f16.f32 "
        "{%0,%1,%2,%3}, {%4,%5,%6,%7}, {%8,%9}, {%0,%1,%2,%3};\n"
        : "+f"(c[0]), "+f"(c[1]), "+f"(c[2]), "+f"(c[3])
        : "r"(a[0]), "r"(a[1]), "r"(a[2]), "r"(a[3]), "r"(b[0]), "r"(b[1]));
}

__device__ __forceinline__ void ldsm_x4(unsigned* r, const __half* p) {
    unsigned a = (unsigned)__cvta_generic_to_shared(p);
    asm volatile(
        "ldmatrix.sync.aligned.m8n8.x4.shared.b16 {%0,%1,%2,%3}, [%4];\n"
        : "=r"(r[0]), "=r"(r[1]), "=r"(r[2]), "=r"(r[3]) : "r"(a));
}

template <bool HALF_OUT>
__global__ __launch_bounds__(256) void gemm_f16(
    const __half* __restrict__ A,
    const __half* __restrict__ B0, const __half* __restrict__ B1,
    const __half* __restrict__ B2,
    void* __restrict__ Cout, int ldc, int coloff_mul)
{
    int z = blockIdx.z;
    const __half* Bm = (z == 0) ? B0 : (z == 1 ? B1 : B2);
    int coloff = z * coloff_mul;

    __shared__ __align__(16) __half As[2][GM][SAH];
    __shared__ __align__(16) __half Bs[2][GN][SAH];

    int tid  = threadIdx.x;
    int lane = tid & 31;
    int warp = tid >> 5;
    int m0 = blockIdx.y * GM;
    int n0 = blockIdx.x * GN;

    int lr = tid >> 1;
    int lc = (tid & 1) * 16;
    const __half* Ag = A  + (size_t)(m0 + lr) * C + lc;
    const __half* Bg = Bm + (size_t)(n0 + lr) * C + lc;

    int m_base = (warp >> 2) * 64;
    int n_base = (warp & 3) * 32;
    int lrow = lane >> 2;
    int lcol = lane & 3;

    // ldmatrix per-lane row/col components
    int a_row = m_base + (lane & 15);        // + mi*16
    int a_k   = (lane >> 4) * 8;             // + ks*16
    int b_row = n_base + (lane >> 4) * 8 + (lane & 7);   // + nip*16
    int b_k   = ((lane >> 3) & 1) * 8;       // + ks*16

    float acc[4][4][4];
    #pragma unroll
    for (int mi = 0; mi < 4; mi++)
        #pragma unroll
        for (int ni = 0; ni < 4; ni++)
            #pragma unroll
            for (int r = 0; r < 4; r++) acc[mi][ni][r] = 0.0f;

    const int nt = C / GKH;   // 16

    uint4 pa0, pa1, pb0, pb1;
    pa0 = *reinterpret_cast<const uint4*>(Ag);
    pa1 = *reinterpret_cast<const uint4*>(Ag + 8);
    pb0 = *reinterpret_cast<const uint4*>(Bg);
    pb1 = *reinterpret_cast<const uint4*>(Bg + 8);

    *reinterpret_cast<uint4*>(&As[0][lr][lc])     = pa0;
    *reinterpret_cast<uint4*>(&As[0][lr][lc + 8]) = pa1;
    *reinterpret_cast<uint4*>(&Bs[0][lr][lc])     = pb0;
    *reinterpret_cast<uint4*>(&Bs[0][lr][lc + 8]) = pb1;
    __syncthreads();

    for (int kt = 0; kt < nt; kt++) {
        int cur = kt & 1;
        bool more = (kt + 1) < nt;
        if (more) {
            const __half* Ap = Ag + (kt + 1) * GKH;
            const __half* Bp = Bg + (kt + 1) * GKH;
            pa0 = *reinterpret_cast<const uint4*>(Ap);
            pa1 = *reinterpret_cast<const uint4*>(Ap + 8);
            pb0 = *reinterpret_cast<const uint4*>(Bp);
            pb1 = *reinterpret_cast<const uint4*>(Bp + 8);
        }

        #pragma unroll
        for (int ks = 0; ks < 2; ks++) {
            unsigned afr[4][4];
            #pragma unroll
            for (int mi = 0; mi < 4; mi++)
                ldsm_x4(afr[mi], &As[cur][a_row + mi * 16][ks * 16 + a_k]);
            unsigned bfr[4][2];
            #pragma unroll
            for (int nip = 0; nip < 2; nip++) {
                unsigned t[4];
                ldsm_x4(t, &Bs[cur][b_row + nip * 16][ks * 16 + b_k]);
                bfr[nip * 2][0]     = t[0];
                bfr[nip * 2][1]     = t[1];
                bfr[nip * 2 + 1][0] = t[2];
                bfr[nip * 2 + 1][1] = t[3];
            }
            #pragma unroll
            for (int mi = 0; mi < 4; mi++)
                #pragma unroll
                for (int ni = 0; ni < 4; ni++)
                    mma_f16(acc[mi][ni], afr[mi], bfr[ni]);
        }

        if (more) {
            int nxt = cur ^ 1;
            *reinterpret_cast<uint4*>(&As[nxt][lr][lc])     = pa0;
            *reinterpret_cast<uint4*>(&As[nxt][lr][lc + 8]) = pa1;
            *reinterpret_cast<uint4*>(&Bs[nxt][lr][lc])     = pb0;
            *reinterpret_cast<uint4*>(&Bs[nxt][lr][lc + 8]) = pb1;
            __syncthreads();
        }
    }

    #pragma unroll
    for (int mi = 0; mi < 4; mi++) {
        #pragma unroll
        for (int ni = 0; ni < 4; ni++) {
            int r  = m0 + m_base + mi * 16 + lrow;
            int cc = coloff + n0 + n_base + ni * 8 + lcol * 2;
            if (HALF_OUT) {
                __half* Ch = (__half*)Cout;
                *reinterpret_cast<__half2*>(Ch + (size_t)r * ldc + cc) =
                    __floats2half2_rn(acc[mi][ni][0], acc[mi][ni][1]);
                *reinterpret_cast<__half2*>(Ch + (size_t)(r + 8) * ldc + cc) =
                    __floats2half2_rn(acc[mi][ni][2], acc[mi][ni][3]);
            } else {
                float* Cf = (float*)Cout;
                *reinterpret_cast<float2*>(Cf + (size_t)r * ldc + cc) =
                    make_float2(acc[mi][ni][0], acc[mi][ni][1]);
                *reinterpret_cast<float2*>(Cf + (size_t)(r + 8) * ldc + cc) =
                    make_float2(acc[mi][ni][2], acc[mi][ni][3]);
            }
        }
    }
}

// ---------------- mask -> per-row compressed (rowoff,val) pairs ------------
// Warp per row; float4 loads + per-component ballot compaction (order-free).
__global__ __launch_bounds__(128) void build_csr(const float* __restrict__ mask)
{
    int row  = blockIdx.x * 4 + (threadIdx.x >> 5);
    int lane = threadIdx.x & 31;

    int cnt = 0;
    const float* mrow = mask + (size_t)row * E;
    float2* prow = g_pair + row * CAP;
    unsigned below = (1u << lane) - 1u;

    float4 v = *reinterpret_cast<const float4*>(mrow + lane * 4);
    for (int j0 = 0; j0 < E; j0 += 128) {
        float4 nv;
        if (j0 + 128 < E)
            nv = *reinterpret_cast<const float4*>(mrow + j0 + 128 + lane * 4);

        unsigned b0 = __ballot_sync(0xFFFFFFFFu, v.x != 0.0f);
        unsigned b1 = __ballot_sync(0xFFFFFFFFu, v.y != 0.0f);
        unsigned b2 = __ballot_sync(0xFFFFFFFFu, v.z != 0.0f);
        unsigned b3 = __ballot_sync(0xFFFFFFFFu, v.w != 0.0f);
        int t0 = __popc(b0), t1 = __popc(b1), t2 = __popc(b2), t3 = __popc(b3);
        int jb = (j0 + lane * 4) * QC;

        if (v.x != 0.0f) {
            int o = cnt + __popc(b0 & below);
            if (o < CAP) prow[o] = make_float2(__int_as_float(jb), v.x);
        }
        if (v.y != 0.0f) {
            int o = cnt + t0 + __popc(b1 & below);
            if (o < CAP) prow[o] = make_float2(__int_as_float(jb + QC), v.y);
        }
        if (v.z != 0.0f) {
            int o = cnt + t0 + t1 + __popc(b2 & below);
            if (o < CAP) prow[o] = make_float2(__int_as_float(jb + 2 * QC), v.z);
        }
        if (v.w != 0.0f) {
            int o = cnt + t0 + t1 + t2 + __popc(b3 & below);
            if (o < CAP) prow[o] = make_float2(__int_as_float(jb + 3 * QC), v.w);
        }
        cnt += t0 + t1 + t2 + t3;
        v = nv;
    }
    if (lane == 0) g_cnt[row] = (cnt > CAP) ? CAP : cnt;
}

// ---------------- vsum: 128-block partial sums (buffer zeroed in conv) -----
__global__ __launch_bounds__(256) void vsum_part()
{
    int bh = blockIdx.x;            // 0..15
    int ch = blockIdx.y;            // 0..7 (e-chunks of 256)
    int b = bh >> 3, h = bh & 7;
    int d2 = threadIdx.x & 31;      // half2 channel pair
    int sl = threadIdx.x >> 5;      // 0..7

    const __half* vb = g_qkv16 + (size_t)b * E * QC + 1024 + h * D + d2 * 2;
    int e0 = ch * 256;
    float sx = 0.0f, sy = 0.0f;
    #pragma unroll 4
    for (int e = e0 + sl; e < e0 + 256; e += 8) {
        float2 f = __half22float2(*reinterpret_cast<const __half2*>(vb + (size_t)e * QC));
        sx += f.x; sy += f.y;
    }
    __shared__ float2 red[8][32];
    red[sl][d2] = make_float2(sx, sy);
    __syncthreads();
    if (sl == 0) {
        float tx = 0.0f, ty = 0.0f;
        #pragma unroll
        for (int i = 0; i < 8; i++) { tx += red[i][d2].x; ty += red[i][d2].y; }
        atomicAdd(&g_vsum[b * C + h * D + d2 * 2],     tx);
        atomicAdd(&g_vsum[b * C + h * D + d2 * 2 + 1], ty);
    }
}

// ---------------- sparse masked attention v7: half2 dot --------------------
__device__ __forceinline__ void h8_to_f(uint4 r, float* f) {
    float2 a = __half22float2(*reinterpret_cast<__half2*>(&r.x));
    float2 b = __half22float2(*reinterpret_cast<__half2*>(&r.y));
    float2 c = __half22float2(*reinterpret_cast<__half2*>(&r.z));
    float2 d = __half22float2(*reinterpret_cast<__half2*>(&r.w));
    f[0] = a.x; f[1] = a.y; f[2] = b.x; f[3] = b.y;
    f[4] = c.x; f[5] = c.y; f[6] = d.x; f[7] = d.y;
}

__device__ __forceinline__ float hdot8(uint4 qr, uint4 kr) {
    const __half2* qh = reinterpret_cast<const __half2*>(&qr);
    const __half2* kh = reinterpret_cast<const __half2*>(&kr);
    __half2 p = __hmul2(qh[0], kh[0]);
    p = __hfma2(qh[1], kh[1], p);
    p = __hfma2(qh[2], kh[2], p);
    p = __hfma2(qh[3], kh[3], p);
    float2 pf = __half22float2(p);
    return pf.x + pf.y;
}

__global__ __launch_bounds__(128) void attn_sparse7()
{
    __shared__ float2 sp[CAP];

    int q   = blockIdx.x;
    int tid = threadIdx.x;        // 0..127
    int bb  = tid >> 6;           // batch 0/1
    int t   = tid & 63;
    int c0  = t * 8;              // channel start (head = c0/64)

    int n    = g_cnt[q];
    int npad = (n + 3) & ~3;
    for (int i = tid; i < npad; i += 128)
        sp[i] = (i < n) ? g_pair[q * CAP + i] : make_float2(__int_as_float(0), 0.0f);
    __syncthreads();

    const __half* kvb = g_qkv16 + (size_t)bb * E * QC;

    uint4 qr = *reinterpret_cast<const uint4*>(kvb + (size_t)q * QC + c0);

    float acc[8];
    {
        float4 a = *reinterpret_cast<const float4*>(g_vsum + bb * C + c0);
        float4 b = *reinterpret_cast<const float4*>(g_vsum + bb * C + c0 + 4);
        acc[0] = 0.5f * a.x; acc[1] = 0.5f * a.y; acc[2] = 0.5f * a.z; acc[3] = 0.5f * a.w;
        acc[4] = 0.5f * b.x; acc[5] = 0.5f * b.y; acc[6] = 0.5f * b.z; acc[7] = 0.5f * b.w;
    }

    const __half* kb = kvb + 512 + c0;   // + rowoff -> k row; +512 more -> v

    for (int i = 0; i < npad; i += 4) {
        float2 pr0 = sp[i], pr1 = sp[i + 1], pr2 = sp[i + 2], pr3 = sp[i + 3];
        const __half* r0 = kb + __float_as_int(pr0.x);
        const __half* r1 = kb + __float_as_int(pr1.x);
        const __half* r2 = kb + __float_as_int(pr2.x);
        const __half* r3 = kb + __float_as_int(pr3.x);

        uint4 kr0 = *reinterpret_cast<const uint4*>(r0);
        uint4 kr1 = *reinterpret_cast<const uint4*>(r1);
        uint4 kr2 = *reinterpret_cast<const uint4*>(r2);
        uint4 kr3 = *reinterpret_cast<const uint4*>(r3);
        uint4 vr0 = *reinterpret_cast<const uint4*>(r0 + 512);
        uint4 vr1 = *reinterpret_cast<const uint4*>(r1 + 512);
        uint4 vr2 = *reinterpret_cast<const uint4*>(r2 + 512);
        uint4 vr3 = *reinterpret_cast<const uint4*>(r3 + 512);

        float p0 = hdot8(qr, kr0);
        float p1 = hdot8(qr, kr1);
        float p2 = hdot8(qr, kr2);
        float p3 = hdot8(qr, kr3);

        #pragma unroll
        for (int o = 1; o < 8; o <<= 1) {
            p0 += __shfl_xor_sync(0xFFFFFFFFu, p0, o, 8);
            p1 += __shfl_xor_sync(0xFFFFFFFFu, p1, o, 8);
            p2 += __shfl_xor_sync(0xFFFFFFFFu, p2, o, 8);
            p3 += __shfl_xor_sync(0xFFFFFFFFu, p3, o, 8);
        }

        float s0 = 0.5f * pr0.y * p0;
        float s1 = 0.5f * pr1.y * p1;
        float s2 = 0.5f * pr2.y * p2;
        float s3 = 0.5f * pr3.y * p3;

        float v0[8], v1[8], v2[8], v3[8];
        h8_to_f(vr0, v0); h8_to_f(vr1, v1); h8_to_f(vr2, v2); h8_to_f(vr3, v3);

        #pragma unroll
        for (int j = 0; j < 8; j++)
            acc[j] += s0 * v0[j] + s1 * v1[j] + s2 * v2[j] + s3 * v3[j];
    }

    uint4 outp;
    __half2* hp = reinterpret_cast<__half2*>(&outp);
    hp[0] = __floats2half2_rn(acc[0], acc[1]);
    hp[1] = __floats2half2_rn(acc[2], acc[3]);
    hp[2] = __floats2half2_rn(acc[4], acc[5]);
    hp[3] = __floats2half2_rn(acc[6], acc[7]);
    *reinterpret_cast<uint4*>(g_o16 + ((size_t)(bb * E + q)) * C + c0) = outp;
}

// ---------------- bias + LayerNorm + residual ------------------------------
__global__ __launch_bounds__(128) void ln_residual(
    const float* __restrict__ x,  const float* __restrict__ bp,
    const float* __restrict__ w,  const float* __restrict__ bb,
    const float* __restrict__ gamma, float* __restrict__ out)
{
    int row = blockIdx.x;          // 0..4095
    int tid = threadIdx.x;         // 128
    const float* pr = g_p + (size_t)row * C;

    float y[4];
    float sum = 0.0f, sq = 0.0f;
    #pragma unroll
    for (int i = 0; i < 4; i++) {
        int c = tid + i * 128;
        y[i] = pr[c] + bp[c];
        sum += y[i];
        sq  += y[i] * y[i];
    }
    #pragma unroll
    for (int o = 16; o; o >>= 1) {
        sum += __shfl_xor_sync(0xFFFFFFFFu, sum, o);
        sq  += __shfl_xor_sync(0xFFFFFFFFu, sq,  o);
    }
    __shared__ float s1[4], s2[4];
    int wid = tid >> 5, lane = tid & 31;
    if (lane == 0) { s1[wid] = sum; s2[wid] = sq; }
    __syncthreads();
    float tot  = s1[0] + s1[1] + s1[2] + s1[3];
    float totq = s2[0] + s2[1] + s2[2] + s2[3];

    float mu  = tot * (1.0f / C);
    float var = totq * (1.0f / C) - mu * mu;
    float rs  = rsqrtf(var + 1e-5f);
    float gm  = gamma[0];

    #pragma unroll
    for (int i = 0; i < 4; i++) {
        int c = tid + i * 128;
        float ln = (y[i] - mu) * rs * w[c] + bb[c];
        out[(size_t)row * C + c] = x[(size_t)row * C + c] + gm * ln;
    }
}

// ---------------- launch ----------------------------------------------------
extern "C" void kernel_launch(void* const* d_in, const int* in_sizes, int n_in,
                              void* d_out, int out_size)
{
    const float* x     = (const float*)d_in[0];
    const float* mask  = (const float*)d_in[1];
    const float* Wq    = (const float*)d_in[2];
    const float* Wk    = (const float*)d_in[3];
    const float* Wv    = (const float*)d_in[4];
    const float* Wp    = (const float*)d_in[5];
    const float* bp    = (const float*)d_in[6];
    const float* lnw   = (const float*)d_in[7];
    const float* lnb   = (const float*)d_in[8];
    const float* gamma = (const float*)d_in[9];
    float* out = (float*)d_out;

    __half *x16p, *w16p, *qkv16p, *o16p;
    float *pp;
    cudaGetSymbolAddress((void**)&x16p, g_x16);
    cudaGetSymbolAddress((void**)&w16p, g_w16);
    cudaGetSymbolAddress((void**)&qkv16p, g_qkv16);
    cudaGetSymbolAddress((void**)&o16p, g_o16);
    cudaGetSymbolAddress((void**)&pp, g_p);

    const int NCONV = (M_TOT * C + 4 * C * C) / 4 / 256;   // 3072 blocks

    // 0) convert x and weights to fp16 (+ zero vsum)
    conv_to_half<<<NCONV, 256>>>(x, Wq, Wk, Wv, Wp);

    // 1) fused QKV projection -> g_qkv16 (fp16)
    gemm_f16<true><<<dim3(C / GN, M_TOT / GM, 3), 256>>>(
        x16p, w16p, w16p + C * C, w16p + 2 * C * C, qkv16p, QC, 512);

    // 2) mask compression (ballot compaction, order-free)
    build_csr<<<E / 4, 128>>>(mask);

    // 3) per-(b,h) V column sums (partial-sum blocks + atomics)
    vsum_part<<<dim3(Bsz * H, 8), 256>>>();

    // 4) sparse masked attention (fp16 gather, half2 dot) -> g_o16
    attn_sparse7<<<E, 128>>>();

    // 5) output projection -> g_p (fp32)
    gemm_f16<false><<<dim3(C / GN, M_TOT / GM, 1), 256>>>(
        o16p, w16p + 3 * C * C, w16p + 3 * C * C, w16p + 3 * C * C, pp, C, 0);

    // 6) bias + LN + residual
    ln_residual<<<M_TOT, 128>>>(x, bp, lnw, lnb, gamma, out);
}

// round 11
// speedup vs baseline: 5.4187x; 1.0152x over previous
#include <cuda_runtime.h>
#include <cuda_fp16.h>

// Problem constants
#define Bsz 2
#define E 2048
#define C 512
#define H 8
#define D 64
#define M_TOT (Bsz * E)       // 4096
#define CAP 320               // per-row nnz capacity (mean ~102)
#define QC 1536               // fused q|k|v half row length

// ---------------- scratch (device globals; no allocation) ----------------
__device__ __half  g_x16[M_TOT * C];        // x in fp16
__device__ __half  g_w16[4 * C * C];        // Wq|Wk|Wv|Wp in fp16
__device__ __half  g_qkv16[M_TOT * QC];     // [row][ q | k | v ] fp16
__device__ __half  g_o16[M_TOT * C];        // attention output, fp16
__device__ float   g_p[M_TOT * C];          // proj output, fp32
__device__ int     g_cnt[E];
__device__ float2  g_pair[E * CAP];         // (rowoffset-as-bits, maskval)
__device__ float   g_vsum[Bsz * C];

// ---------------- fp32 -> fp16 input conversion (+ vsum zeroing) ----------
__global__ __launch_bounds__(256) void conv_to_half(
    const float* __restrict__ x,
    const float* __restrict__ Wq, const float* __restrict__ Wk,
    const float* __restrict__ Wv, const float* __restrict__ Wp)
{
    if (blockIdx.x == 0) {   // also zero the vsum accumulator (1024 floats)
        *reinterpret_cast<float4*>(g_vsum + threadIdx.x * 4) =
            make_float4(0.f, 0.f, 0.f, 0.f);
    }
    int idx = (blockIdx.x * 256 + threadIdx.x) * 4;   // float4 granularity
    const int NX = M_TOT * C;                          // 2^21
    const float* src;
    __half* dst;
    if (idx < NX) {
        src = x + idx;
        dst = g_x16 + idx;
    } else {
        int j = idx - NX;                              // [0, 2^20)
        int region = j >> 18;
        int off = j & ((C * C) - 1);
        src = (region == 0 ? Wq : region == 1 ? Wk : region == 2 ? Wv : Wp) + off;
        dst = g_w16 + j;
    }
    float4 f = *reinterpret_cast<const float4*>(src);
    __half2 h0 = __floats2half2_rn(f.x, f.y);
    __half2 h1 = __floats2half2_rn(f.z, f.w);
    *reinterpret_cast<__half2*>(dst)     = h0;
    *reinterpret_cast<__half2*>(dst + 2) = h1;
}

// =============== fp16 tensor-core GEMM (ldmatrix frag loads) ==============
// C[m, coloff+n] = sum_k A[m,k]*B[n,k].  128x128x32 tiles, double-buffered,
// 256 threads = 8 warps (2m x 4n), warp tile 64x32, mma m16n8k16 f16->f32.
// The v-slice (z==2 of the QKV launch) also folds per-column sums into
// g_vsum via shfl-reduce + atomicAdd (replaces the old vsum kernel).
#define GM 128
#define GN 128
#define GKH 32     // k-halves per tile
#define SAH 40     // padded row stride in halves (80B -> conflict-free LDSM)

__device__ __forceinline__ void mma_f16(float* c, const unsigned* a, const unsigned* b) {
    asm volatile(
        "mma.sync.aligned.m16n8k16.row.col.f32.f16.f16.f32 "
        "{%0,%1,%2,%3}, {%4,%5,%6,%7}, {%8,%9}, {%0,%1,%2,%3};\n"
        : "+f"(c[0]), "+f"(c[1]), "+f"(c[2]), "+f"(c[3])
        : "r"(a[0]), "r"(a[1]), "r"(a[2]), "r"(a[3]), "r"(b[0]), "r"(b[1]));
}

__device__ __forceinline__ void ldsm_x4(unsigned* r, const __half* p) {
    unsigned a = (unsigned)__cvta_generic_to_shared(p);
    asm volatile(
        "ldmatrix.sync.aligned.m8n8.x4.shared.b16 {%0,%1,%2,%3}, [%4];\n"
        : "=r"(r[0]), "=r"(r[1]), "=r"(r[2]), "=r"(r[3]) : "r"(a));
}

template <bool HALF_OUT>
__global__ __launch_bounds__(256) void gemm_f16(
    const __half* __restrict__ A,
    const __half* __restrict__ B0, const __half* __restrict__ B1,
    const __half* __restrict__ B2,
    void* __restrict__ Cout, int ldc, int coloff_mul)
{
    int z = blockIdx.z;
    const __half* Bm = (z == 0) ? B0 : (z == 1 ? B1 : B2);
    int coloff = z * coloff_mul;
    bool dovs = (coloff_mul != 0) && (z == 2);   // v-slice: fold column sums

    __shared__ __align__(16) __half As[2][GM][SAH];
    __shared__ __align__(16) __half Bs[2][GN][SAH];

    int tid  = threadIdx.x;
    int lane = tid & 31;
    int warp = tid >> 5;
    int m0 = blockIdx.y * GM;
    int n0 = blockIdx.x * GN;

    int lr = tid >> 1;
    int lc = (tid & 1) * 16;
    const __half* Ag = A  + (size_t)(m0 + lr) * C + lc;
    const __half* Bg = Bm + (size_t)(n0 + lr) * C + lc;

    int m_base = (warp >> 2) * 64;
    int n_base = (warp & 3) * 32;
    int lrow = lane >> 2;
    int lcol = lane & 3;

    // ldmatrix per-lane row/col components
    int a_row = m_base + (lane & 15);        // + mi*16
    int a_k   = (lane >> 4) * 8;             // + ks*16
    int b_row = n_base + (lane >> 4) * 8 + (lane & 7);   // + nip*16
    int b_k   = ((lane >> 3) & 1) * 8;       // + ks*16

    float acc[4][4][4];
    #pragma unroll
    for (int mi = 0; mi < 4; mi++)
        #pragma unroll
        for (int ni = 0; ni < 4; ni++)
            #pragma unroll
            for (int r = 0; r < 4; r++) acc[mi][ni][r] = 0.0f;

    const int nt = C / GKH;   // 16

    uint4 pa0, pa1, pb0, pb1;
    pa0 = *reinterpret_cast<const uint4*>(Ag);
    pa1 = *reinterpret_cast<const uint4*>(Ag + 8);
    pb0 = *reinterpret_cast<const uint4*>(Bg);
    pb1 = *reinterpret_cast<const uint4*>(Bg + 8);

    *reinterpret_cast<uint4*>(&As[0][lr][lc])     = pa0;
    *reinterpret_cast<uint4*>(&As[0][lr][lc + 8]) = pa1;
    *reinterpret_cast<uint4*>(&Bs[0][lr][lc])     = pb0;
    *reinterpret_cast<uint4*>(&Bs[0][lr][lc + 8]) = pb1;
    __syncthreads();

    for (int kt = 0; kt < nt; kt++) {
        int cur = kt & 1;
        bool more = (kt + 1) < nt;
        if (more) {
            const __half* Ap = Ag + (kt + 1) * GKH;
            const __half* Bp = Bg + (kt + 1) * GKH;
            pa0 = *reinterpret_cast<const uint4*>(Ap);
            pa1 = *reinterpret_cast<const uint4*>(Ap + 8);
            pb0 = *reinterpret_cast<const uint4*>(Bp);
            pb1 = *reinterpret_cast<const uint4*>(Bp + 8);
        }

        #pragma unroll
        for (int ks = 0; ks < 2; ks++) {
            unsigned afr[4][4];
            #pragma unroll
            for (int mi = 0; mi < 4; mi++)
                ldsm_x4(afr[mi], &As[cur][a_row + mi * 16][ks * 16 + a_k]);
            unsigned bfr[4][2];
            #pragma unroll
            for (int nip = 0; nip < 2; nip++) {
                unsigned t[4];
                ldsm_x4(t, &Bs[cur][b_row + nip * 16][ks * 16 + b_k]);
                bfr[nip * 2][0]     = t[0];
                bfr[nip * 2][1]     = t[1];
                bfr[nip * 2 + 1][0] = t[2];
                bfr[nip * 2 + 1][1] = t[3];
            }
            #pragma unroll
            for (int mi = 0; mi < 4; mi++)
                #pragma unroll
                for (int ni = 0; ni < 4; ni++)
                    mma_f16(acc[mi][ni], afr[mi], bfr[ni]);
        }

        if (more) {
            int nxt = cur ^ 1;
            *reinterpret_cast<uint4*>(&As[nxt][lr][lc])     = pa0;
            *reinterpret_cast<uint4*>(&As[nxt][lr][lc + 8]) = pa1;
            *reinterpret_cast<uint4*>(&Bs[nxt][lr][lc])     = pb0;
            *reinterpret_cast<uint4*>(&Bs[nxt][lr][lc + 8]) = pb1;
            __syncthreads();
        }
    }

    #pragma unroll
    for (int mi = 0; mi < 4; mi++) {
        #pragma unroll
        for (int ni = 0; ni < 4; ni++) {
            int r  = m0 + m_base + mi * 16 + lrow;
            int cc = coloff + n0 + n_base + ni * 8 + lcol * 2;
            if (HALF_OUT) {
                __half* Ch = (__half*)Cout;
                *reinterpret_cast<__half2*>(Ch + (size_t)r * ldc + cc) =
                    __floats2half2_rn(acc[mi][ni][0], acc[mi][ni][1]);
                *reinterpret_cast<__half2*>(Ch + (size_t)(r + 8) * ldc + cc) =
                    __floats2half2_rn(acc[mi][ni][2], acc[mi][ni][3]);
            } else {
                float* Cf = (float*)Cout;
                *reinterpret_cast<float2*>(Cf + (size_t)r * ldc + cc) =
                    make_float2(acc[mi][ni][0], acc[mi][ni][1]);
                *reinterpret_cast<float2*>(Cf + (size_t)(r + 8) * ldc + cc) =
                    make_float2(acc[mi][ni][2], acc[mi][ni][3]);
            }
        }
    }

    // fold per-column sums of this 128-row tile into g_vsum (v-slice only)
    if (dovs) {
        int b = m0 >> 11;                       // batch of this row tile
        #pragma unroll
        for (int ni = 0; ni < 4; ni++) {
            float c0s = 0.0f, c1s = 0.0f;
            #pragma unroll
            for (int mi = 0; mi < 4; mi++) {
                c0s += acc[mi][ni][0] + acc[mi][ni][2];
                c1s += acc[mi][ni][1] + acc[mi][ni][3];
            }
            // reduce across lrow (lanes lcol + 4*lrow share a column pair)
            #pragma unroll
            for (int o = 4; o < 32; o <<= 1) {
                c0s += __shfl_xor_sync(0xFFFFFFFFu, c0s, o);
                c1s += __shfl_xor_sync(0xFFFFFFFFu, c1s, o);
            }
            if (lrow == 0) {
                int cn = n0 + n_base + ni * 8 + lcol * 2;
                atomicAdd(&g_vsum[b * C + cn],     c0s);
                atomicAdd(&g_vsum[b * C + cn + 1], c1s);
            }
        }
    }
}

// ---------------- mask -> per-row compressed (rowoff,val) pairs ------------
// Warp per row; float4 loads + per-component ballot compaction (order-free).
__global__ __launch_bounds__(128) void build_csr(const float* __restrict__ mask)
{
    int row  = blockIdx.x * 4 + (threadIdx.x >> 5);
    int lane = threadIdx.x & 31;

    int cnt = 0;
    const float* mrow = mask + (size_t)row * E;
    float2* prow = g_pair + row * CAP;
    unsigned below = (1u << lane) - 1u;

    float4 v = *reinterpret_cast<const float4*>(mrow + lane * 4);
    for (int j0 = 0; j0 < E; j0 += 128) {
        float4 nv;
        if (j0 + 128 < E)
            nv = *reinterpret_cast<const float4*>(mrow + j0 + 128 + lane * 4);

        unsigned b0 = __ballot_sync(0xFFFFFFFFu, v.x != 0.0f);
        unsigned b1 = __ballot_sync(0xFFFFFFFFu, v.y != 0.0f);
        unsigned b2 = __ballot_sync(0xFFFFFFFFu, v.z != 0.0f);
        unsigned b3 = __ballot_sync(0xFFFFFFFFu, v.w != 0.0f);
        int t0 = __popc(b0), t1 = __popc(b1), t2 = __popc(b2), t3 = __popc(b3);
        int jb = (j0 + lane * 4) * QC;

        if (v.x != 0.0f) {
            int o = cnt + __popc(b0 & below);
            if (o < CAP) prow[o] = make_float2(__int_as_float(jb), v.x);
        }
        if (v.y != 0.0f) {
            int o = cnt + t0 + __popc(b1 & below);
            if (o < CAP) prow[o] = make_float2(__int_as_float(jb + QC), v.y);
        }
        if (v.z != 0.0f) {
            int o = cnt + t0 + t1 + __popc(b2 & below);
            if (o < CAP) prow[o] = make_float2(__int_as_float(jb + 2 * QC), v.z);
        }
        if (v.w != 0.0f) {
            int o = cnt + t0 + t1 + t2 + __popc(b3 & below);
            if (o < CAP) prow[o] = make_float2(__int_as_float(jb + 3 * QC), v.w);
        }
        cnt += t0 + t1 + t2 + t3;
        v = nv;
    }
    if (lane == 0) g_cnt[row] = (cnt > CAP) ? CAP : cnt;
}

// ---------------- sparse masked attention v8 -------------------------------
// Block (128 thr) per query q: 2 batches x 64 threads; thread owns 8 channels.
// k-dot in half2; v-axpy in half2 (4-term groups) accumulated into fp32.
__device__ __forceinline__ float hdot8(uint4 qr, uint4 kr) {
    const __half2* qh = reinterpret_cast<const __half2*>(&qr);
    const __half2* kh = reinterpret_cast<const __half2*>(&kr);
    __half2 p = __hmul2(qh[0], kh[0]);
    p = __hfma2(qh[1], kh[1], p);
    p = __hfma2(qh[2], kh[2], p);
    p = __hfma2(qh[3], kh[3], p);
    float2 pf = __half22float2(p);
    return pf.x + pf.y;
}

__global__ __launch_bounds__(128) void attn_sparse8()
{
    __shared__ float2 sp[CAP];

    int q   = blockIdx.x;
    int tid = threadIdx.x;        // 0..127
    int bb  = tid >> 6;           // batch 0/1
    int t   = tid & 63;
    int c0  = t * 8;              // channel start (head = c0/64)

    int n    = g_cnt[q];
    int npad = (n + 3) & ~3;
    for (int i = tid; i < npad; i += 128)
        sp[i] = (i < n) ? g_pair[q * CAP + i] : make_float2(__int_as_float(0), 0.0f);
    __syncthreads();

    const __half* kvb = g_qkv16 + (size_t)bb * E * QC;

    uint4 qr = *reinterpret_cast<const uint4*>(kvb + (size_t)q * QC + c0);

    float acc[8];
    {
        float4 a = *reinterpret_cast<const float4*>(g_vsum + bb * C + c0);
        float4 b = *reinterpret_cast<const float4*>(g_vsum + bb * C + c0 + 4);
        acc[0] = 0.5f * a.x; acc[1] = 0.5f * a.y; acc[2] = 0.5f * a.z; acc[3] = 0.5f * a.w;
        acc[4] = 0.5f * b.x; acc[5] = 0.5f * b.y; acc[6] = 0.5f * b.z; acc[7] = 0.5f * b.w;
    }

    const __half* kb = kvb + 512 + c0;   // + rowoff -> k row; +512 more -> v

    for (int i = 0; i < npad; i += 4) {
        float2 pr0 = sp[i], pr1 = sp[i + 1], pr2 = sp[i + 2], pr3 = sp[i + 3];
        const __half* r0 = kb + __float_as_int(pr0.x);
        const __half* r1 = kb + __float_as_int(pr1.x);
        const __half* r2 = kb + __float_as_int(pr2.x);
        const __half* r3 = kb + __float_as_int(pr3.x);

        uint4 kr0 = *reinterpret_cast<const uint4*>(r0);
        uint4 kr1 = *reinterpret_cast<const uint4*>(r1);
        uint4 kr2 = *reinterpret_cast<const uint4*>(r2);
        uint4 kr3 = *reinterpret_cast<const uint4*>(r3);
        uint4 vr0 = *reinterpret_cast<const uint4*>(r0 + 512);
        uint4 vr1 = *reinterpret_cast<const uint4*>(r1 + 512);
        uint4 vr2 = *reinterpret_cast<const uint4*>(r2 + 512);
        uint4 vr3 = *reinterpret_cast<const uint4*>(r3 + 512);

        float p0 = hdot8(qr, kr0);
        float p1 = hdot8(qr, kr1);
        float p2 = hdot8(qr, kr2);
        float p3 = hdot8(qr, kr3);

        #pragma unroll
        for (int o = 1; o < 8; o <<= 1) {
            p0 += __shfl_xor_sync(0xFFFFFFFFu, p0, o, 8);
            p1 += __shfl_xor_sync(0xFFFFFFFFu, p1, o, 8);
            p2 += __shfl_xor_sync(0xFFFFFFFFu, p2, o, 8);
            p3 += __shfl_xor_sync(0xFFFFFFFFu, p3, o, 8);
        }

        __half2 sh0 = __float2half2_rn(0.5f * pr0.y * p0);
        __half2 sh1 = __float2half2_rn(0.5f * pr1.y * p1);
        __half2 sh2 = __float2half2_rn(0.5f * pr2.y * p2);
        __half2 sh3 = __float2half2_rn(0.5f * pr3.y * p3);

        const __half2* v0h = reinterpret_cast<const __half2*>(&vr0);
        const __half2* v1h = reinterpret_cast<const __half2*>(&vr1);
        const __half2* v2h = reinterpret_cast<const __half2*>(&vr2);
        const __half2* v3h = reinterpret_cast<const __half2*>(&vr3);

        #pragma unroll
        for (int j = 0; j < 4; j++) {
            __half2 a = __hmul2(sh0, v0h[j]);
            a = __hfma2(sh1, v1h[j], a);
            a = __hfma2(sh2, v2h[j], a);
            a = __hfma2(sh3, v3h[j], a);
            float2 f = __half22float2(a);
            acc[2 * j]     += f.x;
            acc[2 * j + 1] += f.y;
        }
    }

    uint4 outp;
    __half2* hp = reinterpret_cast<__half2*>(&outp);
    hp[0] = __floats2half2_rn(acc[0], acc[1]);
    hp[1] = __floats2half2_rn(acc[2], acc[3]);
    hp[2] = __floats2half2_rn(acc[4], acc[5]);
    hp[3] = __floats2half2_rn(acc[6], acc[7]);
    *reinterpret_cast<uint4*>(g_o16 + ((size_t)(bb * E + q)) * C + c0) = outp;
}

// ---------------- bias + LayerNorm + residual (float4) ---------------------
__global__ __launch_bounds__(128) void ln_residual(
    const float* __restrict__ x,  const float* __restrict__ bp,
    const float* __restrict__ w,  const float* __restrict__ bb,
    const float* __restrict__ gamma, float* __restrict__ out)
{
    int row = blockIdx.x;          // 0..4095
    int tid = threadIdx.x;         // 128; thread owns 4 consecutive channels
    int c   = tid * 4;

    float4 y = *reinterpret_cast<const float4*>(g_p + (size_t)row * C + c);
    float4 bv = *reinterpret_cast<const float4*>(bp + c);
    y.x += bv.x; y.y += bv.y; y.z += bv.z; y.w += bv.w;

    float sum = y.x + y.y + y.z + y.w;
    float sq  = y.x * y.x + y.y * y.y + y.z * y.z + y.w * y.w;

    #pragma unroll
    for (int o = 16; o; o >>= 1) {
        sum += __shfl_xor_sync(0xFFFFFFFFu, sum, o);
        sq  += __shfl_xor_sync(0xFFFFFFFFu, sq,  o);
    }
    __shared__ float s1[4], s2[4];
    int wid = tid >> 5, lane = tid & 31;
    if (lane == 0) { s1[wid] = sum; s2[wid] = sq; }
    __syncthreads();
    float tot  = s1[0] + s1[1] + s1[2] + s1[3];
    float totq = s2[0] + s2[1] + s2[2] + s2[3];

    float mu  = tot * (1.0f / C);
    float var = totq * (1.0f / C) - mu * mu;
    float rs  = rsqrtf(var + 1e-5f);
    float gm  = gamma[0];

    float4 wv = *reinterpret_cast<const float4*>(w + c);
    float4 bbv = *reinterpret_cast<const float4*>(bb + c);
    float4 xv = *reinterpret_cast<const float4*>(x + (size_t)row * C + c);
    float4 o;
    o.x = xv.x + gm * ((y.x - mu) * rs * wv.x + bbv.x);
    o.y = xv.y + gm * ((y.y - mu) * rs * wv.y + bbv.y);
    o.z = xv.z + gm * ((y.z - mu) * rs * wv.z + bbv.z);
    o.w = xv.w + gm * ((y.w - mu) * rs * wv.w + bbv.w);
    *reinterpret_cast<float4*>(out + (size_t)row * C + c) = o;
}

// ---------------- launch ----------------------------------------------------
extern "C" void kernel_launch(void* const* d_in, const int* in_sizes, int n_in,
                              void* d_out, int out_size)
{
    const float* x     = (const float*)d_in[0];
    const float* mask  = (const float*)d_in[1];
    const float* Wq    = (const float*)d_in[2];
    const float* Wk    = (const float*)d_in[3];
    const float* Wv    = (const float*)d_in[4];
    const float* Wp    = (const float*)d_in[5];
    const float* bp    = (const float*)d_in[6];
    const float* lnw   = (const float*)d_in[7];
    const float* lnb   = (const float*)d_in[8];
    const float* gamma = (const float*)d_in[9];
    float* out = (float*)d_out;

    __half *x16p, *w16p, *qkv16p, *o16p;
    float *pp;
    cudaGetSymbolAddress((void**)&x16p, g_x16);
    cudaGetSymbolAddress((void**)&w16p, g_w16);
    cudaGetSymbolAddress((void**)&qkv16p, g_qkv16);
    cudaGetSymbolAddress((void**)&o16p, g_o16);
    cudaGetSymbolAddress((void**)&pp, g_p);

    const int NCONV = (M_TOT * C + 4 * C * C) / 4 / 256;   // 3072 blocks

    // 0) convert x and weights to fp16 (+ zero vsum)
    conv_to_half<<<NCONV, 256>>>(x, Wq, Wk, Wv, Wp);

    // 1) fused QKV projection -> g_qkv16 (fp16); v-slice also folds g_vsum
    gemm_f16<true><<<dim3(C / GN, M_TOT / GM, 3), 256>>>(
        x16p, w16p, w16p + C * C, w16p + 2 * C * C, qkv16p, QC, 512);

    // 2) mask compression (ballot compaction, order-free)
    build_csr<<<E / 4, 128>>>(mask);

    // 3) sparse masked attention (fp16 gather, half2 dot+axpy) -> g_o16
    attn_sparse8<<<E, 128>>>();

    // 4) output projection -> g_p (fp32)
    gemm_f16<false><<<dim3(C / GN, M_TOT / GM, 1), 256>>>(
        o16p, w16p + 3 * C * C, w16p + 3 * C * C, w16p + 3 * C * C, pp, C, 0);

    // 5) bias + LN + residual
    ln_residual<<<M_TOT, 128>>>(x, bp, lnw, lnb, gamma, out);
}

// round 12
// speedup vs baseline: 5.4995x; 1.0149x over previous
#include <cuda_runtime.h>
#include <cuda_fp16.h>

// Problem constants
#define Bsz 2
#define E 2048
#define C 512
#define H 8
#define D 64
#define M_TOT (Bsz * E)       // 4096
#define CAP 320               // per-row nnz capacity (mean ~102)
#define QC 1536               // fused q|k|v half row length

// ---------------- scratch (device globals; no allocation) ----------------
__device__ __half  g_x16[M_TOT * C];        // x in fp16
__device__ __half  g_w16[4 * C * C];        // Wq|Wk|Wv|Wp in fp16
__device__ __half  g_qkv16[M_TOT * QC];     // [row][ q | k | v ] fp16
__device__ __half  g_part0[M_TOT * C];      // attention partial 0 (fp16)
__device__ __half  g_part1[M_TOT * C];      // attention partial 1 (fp16)
__device__ float   g_p[M_TOT * C];          // proj output, fp32
__device__ int     g_cnt[E];
__device__ float2  g_pair[E * CAP];         // (rowoffset-as-bits, maskval)
__device__ float   g_vsum[Bsz * C];

// ---------------- fp32 -> fp16 input conversion (+ vsum zeroing) ----------
__global__ __launch_bounds__(256) void conv_to_half(
    const float* __restrict__ x,
    const float* __restrict__ Wq, const float* __restrict__ Wk,
    const float* __restrict__ Wv, const float* __restrict__ Wp)
{
    if (blockIdx.x == 0) {   // also zero the vsum accumulator (1024 floats)
        *reinterpret_cast<float4*>(g_vsum + threadIdx.x * 4) =
            make_float4(0.f, 0.f, 0.f, 0.f);
    }
    int idx = (blockIdx.x * 256 + threadIdx.x) * 4;   // float4 granularity
    const int NX = M_TOT * C;                          // 2^21
    const float* src;
    __half* dst;
    if (idx < NX) {
        src = x + idx;
        dst = g_x16 + idx;
    } else {
        int j = idx - NX;                              // [0, 2^20)
        int region = j >> 18;
        int off = j & ((C * C) - 1);
        src = (region == 0 ? Wq : region == 1 ? Wk : region == 2 ? Wv : Wp) + off;
        dst = g_w16 + j;
    }
    float4 f = *reinterpret_cast<const float4*>(src);
    __half2 h0 = __floats2half2_rn(f.x, f.y);
    __half2 h1 = __floats2half2_rn(f.z, f.w);
    *reinterpret_cast<__half2*>(dst)     = h0;
    *reinterpret_cast<__half2*>(dst + 2) = h1;
}

// =============== fp16 tensor-core GEMM (ldmatrix frag loads) ==============
// C[m, coloff+n] = sum_k A[m,k]*B[n,k].  128x128x32 tiles, double-buffered,
// 256 threads = 8 warps (2m x 4n), warp tile 64x32, mma m16n8k16 f16->f32.
// ADD_A: A operand is the elementwise half-sum of A and A2 (attention
// partials combiner, fused into the smem load). The v-slice (z==2 of the
// QKV launch) folds per-column sums into g_vsum (shfl-reduce + atomicAdd).
#define GM 128
#define GN 128
#define GKH 32     // k-halves per tile
#define SAH 40     // padded row stride in halves (80B -> conflict-free LDSM)

__device__ __forceinline__ void mma_f16(float* c, const unsigned* a, const unsigned* b) {
    asm volatile(
        "mma.sync.aligned.m16n8k16.row.col.f32.f16.f16.f32 "
        "{%0,%1,%2,%3}, {%4,%5,%6,%7}, {%8,%9}, {%0,%1,%2,%3};\n"
        : "+f"(c[0]), "+f"(c[1]), "+f"(c[2]), "+f"(c[3])
        : "r"(a[0]), "r"(a[1]), "r"(a[2]), "r"(a[3]), "r"(b[0]), "r"(b[1]));
}

__device__ __forceinline__ void ldsm_x4(unsigned* r, const __half* p) {
    unsigned a = (unsigned)__cvta_generic_to_shared(p);
    asm volatile(
        "ldmatrix.sync.aligned.m8n8.x4.shared.b16 {%0,%1,%2,%3}, [%4];\n"
        : "=r"(r[0]), "=r"(r[1]), "=r"(r[2]), "=r"(r[3]) : "r"(a));
}

__device__ __forceinline__ uint4 hadd8(uint4 a, uint4 b) {
    uint4 r;
    *reinterpret_cast<__half2*>(&r.x) = __hadd2(
        *reinterpret_cast<__half2*>(&a.x), *reinterpret_cast<__half2*>(&b.x));
    *reinterpret_cast<__half2*>(&r.y) = __hadd2(
        *reinterpret_cast<__half2*>(&a.y), *reinterpret_cast<__half2*>(&b.y));
    *reinterpret_cast<__half2*>(&r.z) = __hadd2(
        *reinterpret_cast<__half2*>(&a.z), *reinterpret_cast<__half2*>(&b.z));
    *reinterpret_cast<__half2*>(&r.w) = __hadd2(
        *reinterpret_cast<__half2*>(&a.w), *reinterpret_cast<__half2*>(&b.w));
    return r;
}

template <bool HALF_OUT, bool ADD_A>
__global__ __launch_bounds__(256) void gemm_f16(
    const __half* __restrict__ A, const __half* __restrict__ A2,
    const __half* __restrict__ B0, const __half* __restrict__ B1,
    const __half* __restrict__ B2,
    void* __restrict__ Cout, int ldc, int coloff_mul)
{
    int z = blockIdx.z;
    const __half* Bm = (z == 0) ? B0 : (z == 1 ? B1 : B2);
    int coloff = z * coloff_mul;
    bool dovs = (coloff_mul != 0) && (z == 2);   // v-slice: fold column sums

    __shared__ __align__(16) __half As[2][GM][SAH];
    __shared__ __align__(16) __half Bs[2][GN][SAH];

    int tid  = threadIdx.x;
    int lane = tid & 31;
    int warp = tid >> 5;
    int m0 = blockIdx.y * GM;
    int n0 = blockIdx.x * GN;

    int lr = tid >> 1;
    int lc = (tid & 1) * 16;
    size_t aoff = (size_t)(m0 + lr) * C + lc;
    const __half* Ag  = A + aoff;
    const __half* Ag2 = ADD_A ? (A2 + aoff) : nullptr;
    const __half* Bg  = Bm + (size_t)(n0 + lr) * C + lc;

    int m_base = (warp >> 2) * 64;
    int n_base = (warp & 3) * 32;
    int lrow = lane >> 2;
    int lcol = lane & 3;

    // ldmatrix per-lane row/col components
    int a_row = m_base + (lane & 15);        // + mi*16
    int a_k   = (lane >> 4) * 8;             // + ks*16
    int b_row = n_base + (lane >> 4) * 8 + (lane & 7);   // + nip*16
    int b_k   = ((lane >> 3) & 1) * 8;       // + ks*16

    float acc[4][4][4];
    #pragma unroll
    for (int mi = 0; mi < 4; mi++)
        #pragma unroll
        for (int ni = 0; ni < 4; ni++)
            #pragma unroll
            for (int r = 0; r < 4; r++) acc[mi][ni][r] = 0.0f;

    const int nt = C / GKH;   // 16

    uint4 pa0, pa1, pb0, pb1;
    pa0 = *reinterpret_cast<const uint4*>(Ag);
    pa1 = *reinterpret_cast<const uint4*>(Ag + 8);
    if (ADD_A) {
        pa0 = hadd8(pa0, *reinterpret_cast<const uint4*>(Ag2));
        pa1 = hadd8(pa1, *reinterpret_cast<const uint4*>(Ag2 + 8));
    }
    pb0 = *reinterpret_cast<const uint4*>(Bg);
    pb1 = *reinterpret_cast<const uint4*>(Bg + 8);

    *reinterpret_cast<uint4*>(&As[0][lr][lc])     = pa0;
    *reinterpret_cast<uint4*>(&As[0][lr][lc + 8]) = pa1;
    *reinterpret_cast<uint4*>(&Bs[0][lr][lc])     = pb0;
    *reinterpret_cast<uint4*>(&Bs[0][lr][lc + 8]) = pb1;
    __syncthreads();

    for (int kt = 0; kt < nt; kt++) {
        int cur = kt & 1;
        bool more = (kt + 1) < nt;
        if (more) {
            const __half* Ap = Ag + (kt + 1) * GKH;
            const __half* Bp = Bg + (kt + 1) * GKH;
            pa0 = *reinterpret_cast<const uint4*>(Ap);
            pa1 = *reinterpret_cast<const uint4*>(Ap + 8);
            if (ADD_A) {
                const __half* Ap2 = Ag2 + (kt + 1) * GKH;
                pa0 = hadd8(pa0, *reinterpret_cast<const uint4*>(Ap2));
                pa1 = hadd8(pa1, *reinterpret_cast<const uint4*>(Ap2 + 8));
            }
            pb0 = *reinterpret_cast<const uint4*>(Bp);
            pb1 = *reinterpret_cast<const uint4*>(Bp + 8);
        }

        #pragma unroll
        for (int ks = 0; ks < 2; ks++) {
            unsigned afr[4][4];
            #pragma unroll
            for (int mi = 0; mi < 4; mi++)
                ldsm_x4(afr[mi], &As[cur][a_row + mi * 16][ks * 16 + a_k]);
            unsigned bfr[4][2];
            #pragma unroll
            for (int nip = 0; nip < 2; nip++) {
                unsigned t[4];
                ldsm_x4(t, &Bs[cur][b_row + nip * 16][ks * 16 + b_k]);
                bfr[nip * 2][0]     = t[0];
                bfr[nip * 2][1]     = t[1];
                bfr[nip * 2 + 1][0] = t[2];
                bfr[nip * 2 + 1][1] = t[3];
            }
            #pragma unroll
            for (int mi = 0; mi < 4; mi++)
                #pragma unroll
                for (int ni = 0; ni < 4; ni++)
                    mma_f16(acc[mi][ni], afr[mi], bfr[ni]);
        }

        if (more) {
            int nxt = cur ^ 1;
            *reinterpret_cast<uint4*>(&As[nxt][lr][lc])     = pa0;
            *reinterpret_cast<uint4*>(&As[nxt][lr][lc + 8]) = pa1;
            *reinterpret_cast<uint4*>(&Bs[nxt][lr][lc])     = pb0;
            *reinterpret_cast<uint4*>(&Bs[nxt][lr][lc + 8]) = pb1;
            __syncthreads();
        }
    }

    #pragma unroll
    for (int mi = 0; mi < 4; mi++) {
        #pragma unroll
        for (int ni = 0; ni < 4; ni++) {
            int r  = m0 + m_base + mi * 16 + lrow;
            int cc = coloff + n0 + n_base + ni * 8 + lcol * 2;
            if (HALF_OUT) {
                __half* Ch = (__half*)Cout;
                *reinterpret_cast<__half2*>(Ch + (size_t)r * ldc + cc) =
                    __floats2half2_rn(acc[mi][ni][0], acc[mi][ni][1]);
                *reinterpret_cast<__half2*>(Ch + (size_t)(r + 8) * ldc + cc) =
                    __floats2half2_rn(acc[mi][ni][2], acc[mi][ni][3]);
            } else {
                float* Cf = (float*)Cout;
                *reinterpret_cast<float2*>(Cf + (size_t)r * ldc + cc) =
                    make_float2(acc[mi][ni][0], acc[mi][ni][1]);
                *reinterpret_cast<float2*>(Cf + (size_t)(r + 8) * ldc + cc) =
                    make_float2(acc[mi][ni][2], acc[mi][ni][3]);
            }
        }
    }

    // fold per-column sums of this 128-row tile into g_vsum (v-slice only)
    if (dovs) {
        int b = m0 >> 11;                       // batch of this row tile
        #pragma unroll
        for (int ni = 0; ni < 4; ni++) {
            float c0s = 0.0f, c1s = 0.0f;
            #pragma unroll
            for (int mi = 0; mi < 4; mi++) {
                c0s += acc[mi][ni][0] + acc[mi][ni][2];
                c1s += acc[mi][ni][1] + acc[mi][ni][3];
            }
            // reduce across lrow (lanes lcol + 4*lrow share a column pair)
            #pragma unroll
            for (int o = 4; o < 32; o <<= 1) {
                c0s += __shfl_xor_sync(0xFFFFFFFFu, c0s, o);
                c1s += __shfl_xor_sync(0xFFFFFFFFu, c1s, o);
            }
            if (lrow == 0) {
                int cn = n0 + n_base + ni * 8 + lcol * 2;
                atomicAdd(&g_vsum[b * C + cn],     c0s);
                atomicAdd(&g_vsum[b * C + cn + 1], c1s);
            }
        }
    }
}

// ---------------- mask -> per-row compressed (rowoff,val) pairs ------------
// Warp per row; float4 loads + per-component ballot compaction (order-free).
__global__ __launch_bounds__(128) void build_csr(const float* __restrict__ mask)
{
    int row  = blockIdx.x * 4 + (threadIdx.x >> 5);
    int lane = threadIdx.x & 31;

    int cnt = 0;
    const float* mrow = mask + (size_t)row * E;
    float2* prow = g_pair + row * CAP;
    unsigned below = (1u << lane) - 1u;

    float4 v = *reinterpret_cast<const float4*>(mrow + lane * 4);
    for (int j0 = 0; j0 < E; j0 += 128) {
        float4 nv;
        if (j0 + 128 < E)
            nv = *reinterpret_cast<const float4*>(mrow + j0 + 128 + lane * 4);

        unsigned b0 = __ballot_sync(0xFFFFFFFFu, v.x != 0.0f);
        unsigned b1 = __ballot_sync(0xFFFFFFFFu, v.y != 0.0f);
        unsigned b2 = __ballot_sync(0xFFFFFFFFu, v.z != 0.0f);
        unsigned b3 = __ballot_sync(0xFFFFFFFFu, v.w != 0.0f);
        int t0 = __popc(b0), t1 = __popc(b1), t2 = __popc(b2), t3 = __popc(b3);
        int jb = (j0 + lane * 4) * QC;

        if (v.x != 0.0f) {
            int o = cnt + __popc(b0 & below);
            if (o < CAP) prow[o] = make_float2(__int_as_float(jb), v.x);
        }
        if (v.y != 0.0f) {
            int o = cnt + t0 + __popc(b1 & below);
            if (o < CAP) prow[o] = make_float2(__int_as_float(jb + QC), v.y);
        }
        if (v.z != 0.0f) {
            int o = cnt + t0 + t1 + __popc(b2 & below);
            if (o < CAP) prow[o] = make_float2(__int_as_float(jb + 2 * QC), v.z);
        }
        if (v.w != 0.0f) {
            int o = cnt + t0 + t1 + t2 + __popc(b3 & below);
            if (o < CAP) prow[o] = make_float2(__int_as_float(jb + 3 * QC), v.w);
        }
        cnt += t0 + t1 + t2 + t3;
        v = nv;
    }
    if (lane == 0) g_cnt[row] = (cnt > CAP) ? CAP : cnt;
}

// ---------------- sparse masked attention v9: split lists ------------------
// Grid (E, 2): block (q, z) processes list entries {4z, 4z+8, ...} (4/iter).
// 128 threads = 2 batches x 64; thread owns 8 channels. z=0 seeds 0.5*vsum.
// Partials land in g_part0 / g_part1; the proj GEMM sums them on load.
__device__ __forceinline__ float hdot8(uint4 qr, uint4 kr) {
    const __half2* qh = reinterpret_cast<const __half2*>(&qr);
    const __half2* kh = reinterpret_cast<const __half2*>(&kr);
    __half2 p = __hmul2(qh[0], kh[0]);
    p = __hfma2(qh[1], kh[1], p);
    p = __hfma2(qh[2], kh[2], p);
    p = __hfma2(qh[3], kh[3], p);
    float2 pf = __half22float2(p);
    return pf.x + pf.y;
}

__global__ __launch_bounds__(128) void attn_sparse9()
{
    __shared__ float2 sp[CAP];

    int q   = blockIdx.x;
    int zz  = blockIdx.y;         // list half 0/1
    int tid = threadIdx.x;        // 0..127
    int bb  = tid >> 6;           // batch 0/1
    int t   = tid & 63;
    int c0  = t * 8;              // channel start (head = c0/64)

    int n    = g_cnt[q];
    int npad = (n + 3) & ~3;
    for (int i = tid; i < npad; i += 128)
        sp[i] = (i < n) ? g_pair[q * CAP + i] : make_float2(__int_as_float(0), 0.0f);
    __syncthreads();

    const __half* kvb = g_qkv16 + (size_t)bb * E * QC;

    uint4 qr = *reinterpret_cast<const uint4*>(kvb + (size_t)q * QC + c0);

    float acc[8];
    if (zz == 0) {
        float4 a = *reinterpret_cast<const float4*>(g_vsum + bb * C + c0);
        float4 b = *reinterpret_cast<const float4*>(g_vsum + bb * C + c0 + 4);
        acc[0] = 0.5f * a.x; acc[1] = 0.5f * a.y; acc[2] = 0.5f * a.z; acc[3] = 0.5f * a.w;
        acc[4] = 0.5f * b.x; acc[5] = 0.5f * b.y; acc[6] = 0.5f * b.z; acc[7] = 0.5f * b.w;
    } else {
        #pragma unroll
        for (int j = 0; j < 8; j++) acc[j] = 0.0f;
    }

    const __half* kb = kvb + 512 + c0;   // + rowoff -> k row; +512 more -> v

    for (int i = zz * 4; i < npad; i += 8) {
        float2 pr0 = sp[i], pr1 = sp[i + 1], pr2 = sp[i + 2], pr3 = sp[i + 3];
        const __half* r0 = kb + __float_as_int(pr0.x);
        const __half* r1 = kb + __float_as_int(pr1.x);
        const __half* r2 = kb + __float_as_int(pr2.x);
        const __half* r3 = kb + __float_as_int(pr3.x);

        uint4 kr0 = *reinterpret_cast<const uint4*>(r0);
        uint4 kr1 = *reinterpret_cast<const uint4*>(r1);
        uint4 kr2 = *reinterpret_cast<const uint4*>(r2);
        uint4 kr3 = *reinterpret_cast<const uint4*>(r3);
        uint4 vr0 = *reinterpret_cast<const uint4*>(r0 + 512);
        uint4 vr1 = *reinterpret_cast<const uint4*>(r1 + 512);
        uint4 vr2 = *reinterpret_cast<const uint4*>(r2 + 512);
        uint4 vr3 = *reinterpret_cast<const uint4*>(r3 + 512);

        float p0 = hdot8(qr, kr0);
        float p1 = hdot8(qr, kr1);
        float p2 = hdot8(qr, kr2);
        float p3 = hdot8(qr, kr3);

        #pragma unroll
        for (int o = 1; o < 8; o <<= 1) {
            p0 += __shfl_xor_sync(0xFFFFFFFFu, p0, o, 8);
            p1 += __shfl_xor_sync(0xFFFFFFFFu, p1, o, 8);
            p2 += __shfl_xor_sync(0xFFFFFFFFu, p2, o, 8);
            p3 += __shfl_xor_sync(0xFFFFFFFFu, p3, o, 8);
        }

        __half2 sh0 = __float2half2_rn(0.5f * pr0.y * p0);
        __half2 sh1 = __float2half2_rn(0.5f * pr1.y * p1);
        __half2 sh2 = __float2half2_rn(0.5f * pr2.y * p2);
        __half2 sh3 = __float2half2_rn(0.5f * pr3.y * p3);

        const __half2* v0h = reinterpret_cast<const __half2*>(&vr0);
        const __half2* v1h = reinterpret_cast<const __half2*>(&vr1);
        const __half2* v2h = reinterpret_cast<const __half2*>(&vr2);
        const __half2* v3h = reinterpret_cast<const __half2*>(&vr3);

        #pragma unroll
        for (int j = 0; j < 4; j++) {
            __half2 a = __hmul2(sh0, v0h[j]);
            a = __hfma2(sh1, v1h[j], a);
            a = __hfma2(sh2, v2h[j], a);
            a = __hfma2(sh3, v3h[j], a);
            float2 f = __half22float2(a);
            acc[2 * j]     += f.x;
            acc[2 * j + 1] += f.y;
        }
    }

    uint4 outp;
    __half2* hp = reinterpret_cast<__half2*>(&outp);
    hp[0] = __floats2half2_rn(acc[0], acc[1]);
    hp[1] = __floats2half2_rn(acc[2], acc[3]);
    hp[2] = __floats2half2_rn(acc[4], acc[5]);
    hp[3] = __floats2half2_rn(acc[6], acc[7]);
    __half* dst = zz ? g_part1 : g_part0;
    *reinterpret_cast<uint4*>(dst + ((size_t)(bb * E + q)) * C + c0) = outp;
}

// ---------------- bias + LayerNorm + residual (float4) ---------------------
__global__ __launch_bounds__(128) void ln_residual(
    const float* __restrict__ x,  const float* __restrict__ bp,
    const float* __restrict__ w,  const float* __restrict__ bb,
    const float* __restrict__ gamma, float* __restrict__ out)
{
    int row = blockIdx.x;          // 0..4095
    int tid = threadIdx.x;         // 128; thread owns 4 consecutive channels
    int c   = tid * 4;

    float4 y = *reinterpret_cast<const float4*>(g_p + (size_t)row * C + c);
    float4 bv = *reinterpret_cast<const float4*>(bp + c);
    y.x += bv.x; y.y += bv.y; y.z += bv.z; y.w += bv.w;

    float sum = y.x + y.y + y.z + y.w;
    float sq  = y.x * y.x + y.y * y.y + y.z * y.z + y.w * y.w;

    #pragma unroll
    for (int o = 16; o; o >>= 1) {
        sum += __shfl_xor_sync(0xFFFFFFFFu, sum, o);
        sq  += __shfl_xor_sync(0xFFFFFFFFu, sq,  o);
    }
    __shared__ float s1[4], s2[4];
    int wid = tid >> 5, lane = tid & 31;
    if (lane == 0) { s1[wid] = sum; s2[wid] = sq; }
    __syncthreads();
    float tot  = s1[0] + s1[1] + s1[2] + s1[3];
    float totq = s2[0] + s2[1] + s2[2] + s2[3];

    float mu  = tot * (1.0f / C);
    float var = totq * (1.0f / C) - mu * mu;
    float rs  = rsqrtf(var + 1e-5f);
    float gm  = gamma[0];

    float4 wv = *reinterpret_cast<const float4*>(w + c);
    float4 bbv = *reinterpret_cast<const float4*>(bb + c);
    float4 xv = *reinterpret_cast<const float4*>(x + (size_t)row * C + c);
    float4 o;
    o.x = xv.x + gm * ((y.x - mu) * rs * wv.x + bbv.x);
    o.y = xv.y + gm * ((y.y - mu) * rs * wv.y + bbv.y);
    o.z = xv.z + gm * ((y.z - mu) * rs * wv.z + bbv.z);
    o.w = xv.w + gm * ((y.w - mu) * rs * wv.w + bbv.w);
    *reinterpret_cast<float4*>(out + (size_t)row * C + c) = o;
}

// ---------------- launch ----------------------------------------------------
extern "C" void kernel_launch(void* const* d_in, const int* in_sizes, int n_in,
                              void* d_out, int out_size)
{
    const float* x     = (const float*)d_in[0];
    const float* mask  = (const float*)d_in[1];
    const float* Wq    = (const float*)d_in[2];
    const float* Wk    = (const float*)d_in[3];
    const float* Wv    = (const float*)d_in[4];
    const float* Wp    = (const float*)d_in[5];
    const float* bp    = (const float*)d_in[6];
    const float* lnw   = (const float*)d_in[7];
    const float* lnb   = (const float*)d_in[8];
    const float* gamma = (const float*)d_in[9];
    float* out = (float*)d_out;

    __half *x16p, *w16p, *qkv16p, *p0p, *p1p;
    float *pp;
    cudaGetSymbolAddress((void**)&x16p, g_x16);
    cudaGetSymbolAddress((void**)&w16p, g_w16);
    cudaGetSymbolAddress((void**)&qkv16p, g_qkv16);
    cudaGetSymbolAddress((void**)&p0p, g_part0);
    cudaGetSymbolAddress((void**)&p1p, g_part1);
    cudaGetSymbolAddress((void**)&pp, g_p);

    const int NCONV = (M_TOT * C + 4 * C * C) / 4 / 256;   // 3072 blocks

    // 0) convert x and weights to fp16 (+ zero vsum)
    conv_to_half<<<NCONV, 256>>>(x, Wq, Wk, Wv, Wp);

    // 1) fused QKV projection -> g_qkv16 (fp16); v-slice also folds g_vsum
    gemm_f16<true, false><<<dim3(C / GN, M_TOT / GM, 3), 256>>>(
        x16p, nullptr, w16p, w16p + C * C, w16p + 2 * C * C, qkv16p, QC, 512);

    // 2) mask compression (ballot compaction, order-free)
    build_csr<<<E / 4, 128>>>(mask);

    // 3) sparse masked attention, list split across 2 blocks -> g_part0/1
    attn_sparse9<<<dim3(E, 2), 128>>>();

    // 4) output projection (A = part0 + part1, fused) -> g_p (fp32)
    gemm_f16<false, true><<<dim3(C / GN, M_TOT / GM, 1), 256>>>(
        p0p, p1p, w16p + 3 * C * C, w16p + 3 * C * C, w16p + 3 * C * C, pp, C, 0);

    // 5) bias + LN + residual
    ln_residual<<<M_TOT, 128>>>(x, bp, lnw, lnb, gamma, out);
}